// round 11
// baseline (speedup 1.0000x reference)
#include <cuda_runtime.h>
#include <cuda_bf16.h>
#include <math.h>
#include <stdint.h>

#define NN 8192
#define CHID 256
#define CACT 128
#define EMAX 262144

// ---------------- scratch (no allocations allowed) ----------------
__device__ float g_X [NN * 32];
__device__ float g_S1[NN * CHID];
__device__ float g_G1[NN * CHID];
__device__ float g_S2[NN * CACT];
__device__ float g_G2[NN * CACT];
__device__ __align__(16) __nv_bfloat16 g_Zb1[NN * CACT];
__device__ __align__(16) __nv_bfloat16 g_Zb2[NN * CACT];
__device__ float g_rs11[NN], g_rs22[NN], g_rs12[NN], g_cs12[NN];
__device__ float g_d11[NN], g_d22[NN], g_d12[NN];
__device__ int g_cnt[NN];
__device__ int g_cur[NN];
__device__ int g_rowstart[2 * (NN + 1)];
__device__ int g_eidx[2 * EMAX];

// ================= warp-MMA helpers (sm_80+ PTX, safe for compute_103) =================
__device__ __forceinline__ uint32_t smem_u32(const void* p) {
    uint32_t a;
    asm("{ .reg .u64 t; cvta.to.shared.u64 t, %1; cvt.u32.u64 %0, t; }" : "=r"(a) : "l"(p));
    return a;
}
__device__ __forceinline__ void ldsm_x4(uint32_t& r0, uint32_t& r1, uint32_t& r2, uint32_t& r3,
                                        uint32_t saddr) {
    asm volatile("ldmatrix.sync.aligned.m8n8.x4.shared.b16 {%0,%1,%2,%3}, [%4];"
                 : "=r"(r0), "=r"(r1), "=r"(r2), "=r"(r3) : "r"(saddr));
}
__device__ __forceinline__ void mma16816(float* c, uint32_t a0, uint32_t a1, uint32_t a2,
                                         uint32_t a3, uint32_t b0, uint32_t b1) {
    asm volatile(
        "mma.sync.aligned.m16n8k16.row.col.f32.bf16.bf16.f32 "
        "{%0,%1,%2,%3}, {%4,%5,%6,%7}, {%8,%9}, {%0,%1,%2,%3};"
        : "+f"(c[0]), "+f"(c[1]), "+f"(c[2]), "+f"(c[3])
        : "r"(a0), "r"(a1), "r"(a2), "r"(a3), "r"(b0), "r"(b1));
}

// ---------------- MLP: x = relu(feat@w1+b1)@w2+b2  (512->64->32), 4 rows/block ----------------
__global__ void k_mlp(const float* __restrict__ feat,
                      const float* __restrict__ w1, const float* __restrict__ b1,
                      const float* __restrict__ w2, const float* __restrict__ b2,
                      float* __restrict__ xout)
{
    __shared__ float sf[4 * 512];
    __shared__ float t1[4][64];
    int tid = threadIdx.x;           // 64 threads
    int r0 = blockIdx.x * 4;
    const float4* f4 = (const float4*)(feat + (size_t)r0 * 512);
    #pragma unroll
    for (int i = 0; i < 8; i++)
        ((float4*)sf)[tid + i * 64] = f4[tid + i * 64];
    __syncthreads();
    float a0 = b1[tid], a1 = a0, a2 = a0, a3 = a0;
    #pragma unroll 4
    for (int k = 0; k < 512; k++) {
        float wv = w1[k * 64 + tid];
        a0 = fmaf(sf[k], wv, a0);
        a1 = fmaf(sf[512 + k], wv, a1);
        a2 = fmaf(sf[1024 + k], wv, a2);
        a3 = fmaf(sf[1536 + k], wv, a3);
    }
    t1[0][tid] = fmaxf(a0, 0.f); t1[1][tid] = fmaxf(a1, 0.f);
    t1[2][tid] = fmaxf(a2, 0.f); t1[3][tid] = fmaxf(a3, 0.f);
    __syncthreads();
    #pragma unroll
    for (int t = tid; t < 128; t += 64) {
        int r = t >> 5, o = t & 31;
        float acc = b2[o];
        #pragma unroll
        for (int k = 0; k < 64; k++)
            acc = fmaf(t1[r][k], w2[k * 32 + o], acc);
        xout[(r0 + r) * 32 + o] = acc;
    }
}

// ---------------- support1 = x @ w_g1  (32 -> 256), one row/block ----------------
__global__ void k_sup1(const float* __restrict__ x, const float* __restrict__ w,
                       float* __restrict__ sup)
{
    __shared__ float sx[32];
    int tid = threadIdx.x;           // 256
    int row = blockIdx.x;
    if (tid < 32) sx[tid] = x[row * 32 + tid];
    __syncthreads();
    float acc = 0.f;
    #pragma unroll
    for (int k = 0; k < 32; k++)
        acc = fmaf(sx[k], w[k * 256 + tid], acc);
    sup[row * 256 + tid] = acc;
}

// ---------------- CSR build ----------------
__global__ void k_zcnt(int* __restrict__ cnt)
{
    int i = blockIdx.x * blockDim.x + threadIdx.x;
    if (i < NN) cnt[i] = 0;
}
__global__ void k_hist(const int* __restrict__ ei, int* __restrict__ cnt, int E)
{
    int e = blockIdx.x * blockDim.x + threadIdx.x;
    if (e < E) atomicAdd(&cnt[ei[e]], 1);
}
__global__ void k_scan(const int* __restrict__ cnt, int* __restrict__ rowstart,
                       int* __restrict__ cur)
{
    __shared__ int ps[1024];
    int t = threadIdx.x;             // 1024 threads
    int loc[8]; int s = 0;
    #pragma unroll
    for (int j = 0; j < 8; j++) { loc[j] = s; s += cnt[t * 8 + j]; }
    ps[t] = s;
    __syncthreads();
    for (int off = 1; off < 1024; off <<= 1) {
        int v = (t >= off) ? ps[t - off] : 0;
        __syncthreads();
        ps[t] += v;
        __syncthreads();
    }
    int b = ps[t] - s;               // exclusive base
    #pragma unroll
    for (int j = 0; j < 8; j++) { rowstart[t * 8 + j] = b + loc[j]; cur[t * 8 + j] = b + loc[j]; }
    if (t == 1023) rowstart[NN] = ps[1023];
}
__global__ void k_fill(const int* __restrict__ ei, int* __restrict__ cur,
                       int* __restrict__ eidx, int E)
{
    int e = blockIdx.x * blockDim.x + threadIdx.x;
    if (e >= E) return;
    int p = atomicAdd(&cur[ei[e]], 1);
    eidx[p] = e;
}

// ---------------- CSR gather: out[r][c] = b[c] + sum_e w_e * sup[src_e][c] ----------------
__global__ void k_gather(const int* __restrict__ rowstart, const int* __restrict__ eidx,
                         const int* __restrict__ ei, const float* __restrict__ ew,
                         const float* __restrict__ sup, const float* __restrict__ bias,
                         float* __restrict__ out, int E, int C)
{
    __shared__ int ssrc[128];
    __shared__ float swt[128];
    int r = blockIdx.x, c = threadIdx.x;     // C threads
    int s0 = rowstart[r], s1 = rowstart[r + 1];
    float acc = bias[c];
    for (int base = s0; base < s1; base += 128) {
        int len = min(128, s1 - base);
        __syncthreads();
        if (c < len) {
            int e = eidx[base + c];
            ssrc[c] = ei[E + e];
            swt[c]  = ew[e];
        }
        __syncthreads();
        for (int i = 0; i < len; i++)
            acc = fmaf(swt[i], sup[(size_t)ssrc[i] * C + c], acc);
    }
    out[(size_t)r * C + c] = acc;
}

// ---------------- support2 = relu(h) @ w_g2  (256 -> 128), 4 rows/block ----------------
__global__ void k_sup2(const float* __restrict__ h, const float* __restrict__ w,
                       float* __restrict__ sup)
{
    __shared__ float sh[4 * 256];
    int tid = threadIdx.x;           // 128
    int r0 = blockIdx.x * 4;
    #pragma unroll
    for (int i = tid; i < 1024; i += 128)
        sh[i] = fmaxf(h[(size_t)r0 * 256 + i], 0.f);
    __syncthreads();
    float a0 = 0, a1 = 0, a2 = 0, a3 = 0;
    #pragma unroll 4
    for (int k = 0; k < 256; k++) {
        float wv = w[k * 128 + tid];
        a0 = fmaf(sh[k], wv, a0);
        a1 = fmaf(sh[256 + k], wv, a1);
        a2 = fmaf(sh[512 + k], wv, a2);
        a3 = fmaf(sh[768 + k], wv, a3);
    }
    sup[(r0 + 0) * 128 + tid] = a0;
    sup[(r0 + 1) * 128 + tid] = a1;
    sup[(r0 + 2) * 128 + tid] = a2;
    sup[(r0 + 3) * 128 + tid] = a3;
}

// ---------------- proj + L2 normalize -> bf16 ----------------
__global__ void k_proj(const float* __restrict__ h,
                       const float* __restrict__ w1, const float* __restrict__ b1,
                       const float* __restrict__ w2, const float* __restrict__ b2,
                       __nv_bfloat16* __restrict__ zb)
{
    __shared__ float sh[128];
    __shared__ float t[64];
    __shared__ float red[128];
    int tid = threadIdx.x;           // 128
    int row = blockIdx.x;
    sh[tid] = h[row * 128 + tid];
    __syncthreads();
    if (tid < 64) {
        float a = b1[tid];
        #pragma unroll
        for (int k = 0; k < 128; k++)
            a = fmaf(sh[k], w1[k * 64 + tid], a);
        t[tid] = a > 0.f ? a : expm1f(a);
    }
    __syncthreads();
    float a = b2[tid];
    #pragma unroll
    for (int k = 0; k < 64; k++)
        a = fmaf(t[k], w2[k * 128 + tid], a);
    red[tid] = a * a;
    __syncthreads();
    for (int st = 64; st; st >>= 1) {
        if (tid < st) red[tid] += red[tid + st];
        __syncthreads();
    }
    float inv = 1.f / fmaxf(sqrtf(red[0]), 1e-12f);
    zb[row * 128 + tid] = __float2bfloat16(a * inv);
}

// ---------------- zero accumulators ----------------
__global__ void k_zero4(float* a, float* b, float* c, float* d)
{
    int i = blockIdx.x * blockDim.x + threadIdx.x;
    if (i < NN) { a[i] = 0.f; b[i] = 0.f; c[i] = 0.f; d[i] = 0.f; }
}

// ---------------- bf16 HMMA pairwise exp row/col-sums (symmetry-reduced) ----------------
// job0: Z1 Z1^T (sym, tj>=ti) -> rs11 (+d11). off-diag col sums feed rows of tj block.
// job1: Z2 Z2^T (sym, tj>=ti) -> rs22 (+d22). same.
// job2: Z1 Z2^T (full)        -> row sums rs12 (+d12), col sums cs12 (replaces old job3).
// Block: 128x128 tile, 256 threads = 8 warps (4M x 2N), warp tile 32x64.
#define LDS_PAIR 136
__global__ void __launch_bounds__(256) k_pair_mma(
    const __nv_bfloat16* __restrict__ Zb1, const __nv_bfloat16* __restrict__ Zb2,
    float* __restrict__ rs11, float* __restrict__ d11,
    float* __restrict__ rs22, float* __restrict__ d22,
    float* __restrict__ rs12, float* __restrict__ d12,
    float* __restrict__ cs12)
{
    int job = blockIdx.z, ti = blockIdx.y, tj = blockIdx.x;
    bool sym = (job < 2);
    if (sym && tj < ti) return;

    extern __shared__ __nv_bfloat16 smp[];
    __nv_bfloat16* As = smp;                       // 128 x 136
    __nv_bfloat16* Bs = smp + 128 * LDS_PAIR;      // 128 x 136

    int tid = threadIdx.x, wid = tid >> 5, lane = tid & 31;
    int wm = wid >> 1, wn = wid & 1;               // warp grid 4x2

    const __nv_bfloat16* A = (job == 1) ? Zb2 : Zb1;
    const __nv_bfloat16* B = (job == 0) ? Zb1 : Zb2;
    float* RS = (job == 0) ? rs11 : (job == 1) ? rs22 : rs12;
    float* CS = (job == 0) ? rs11 : (job == 1) ? rs22 : cs12;
    float* DG = (job == 0) ? d11 : (job == 1) ? d22 : d12;
    bool dtile = (ti == tj);
    // col sums needed: sym off-diag (feeds tj-block rows) and always for job2 (cs12)
    bool docol = (job == 2) || (tj > ti);

    // load 128x128 bf16 tiles (uint4 = 8 bf16 per thread-iter)
    const __nv_bfloat16* Ap = A + (size_t)ti * 128 * 128;
    const __nv_bfloat16* Bp = B + (size_t)tj * 128 * 128;
    #pragma unroll
    for (int it = 0; it < 8; it++) {
        int idx = it * 256 + tid;
        int row = idx >> 4, col8 = (idx & 15) * 8;
        *(uint4*)(As + row * LDS_PAIR + col8) = *(const uint4*)(Ap + (size_t)row * 128 + col8);
        *(uint4*)(Bs + row * LDS_PAIR + col8) = *(const uint4*)(Bp + (size_t)row * 128 + col8);
    }
    __syncthreads();

    float acc[2][8][4];
    #pragma unroll
    for (int mt = 0; mt < 2; mt++)
        #pragma unroll
        for (int nt = 0; nt < 8; nt++)
            #pragma unroll
            for (int q = 0; q < 4; q++) acc[mt][nt][q] = 0.f;

    uint32_t a_base = smem_u32(As);
    uint32_t b_base = smem_u32(Bs);
    int lrow = lane & 15, lcol = (lane >> 4) * 8;

    #pragma unroll
    for (int ks = 0; ks < 8; ks++) {
        int k0 = ks * 16;
        uint32_t af[2][4];
        #pragma unroll
        for (int mt = 0; mt < 2; mt++) {
            uint32_t addr = a_base + ((wm * 32 + mt * 16 + lrow) * LDS_PAIR + k0 + lcol) * 2;
            ldsm_x4(af[mt][0], af[mt][1], af[mt][2], af[mt][3], addr);
        }
        uint32_t bf[8][2];
        #pragma unroll
        for (int p = 0; p < 4; p++) {
            uint32_t r0, r1, r2, r3;
            uint32_t addr = b_base + ((wn * 64 + p * 16 + lrow) * LDS_PAIR + k0 + lcol) * 2;
            ldsm_x4(r0, r1, r2, r3, addr);
            bf[2 * p][0] = r0; bf[2 * p][1] = r2;
            bf[2 * p + 1][0] = r1; bf[2 * p + 1][1] = r3;
        }
        #pragma unroll
        for (int mt = 0; mt < 2; mt++)
            #pragma unroll
            for (int nt = 0; nt < 8; nt++)
                mma16816(acc[mt][nt], af[mt][0], af[mt][1], af[mt][2], af[mt][3],
                         bf[nt][0], bf[nt][1]);
    }

    // epilogue: e = exp(2*s); row sums always; col sums when docol; diag capture
    int qp = lane & 3, qr = lane >> 2;
    float rsum[2][2] = {{0.f, 0.f}, {0.f, 0.f}};
    float csum[8][2];
    #pragma unroll
    for (int nt = 0; nt < 8; nt++) { csum[nt][0] = 0.f; csum[nt][1] = 0.f; }

    #pragma unroll
    for (int mt = 0; mt < 2; mt++) {
        #pragma unroll
        for (int nt = 0; nt < 8; nt++) {
            #pragma unroll
            for (int q = 0; q < 4; q++) {
                float e = __expf(2.0f * acc[mt][nt][q]);   // 1/TEMP = 2
                rsum[mt][q >> 1] += e;
                csum[nt][q & 1] += e;
                if (dtile) {
                    int col = wn * 64 + nt * 8 + qp * 2 + (q & 1);
                    int row = wm * 32 + mt * 16 + qr + (q >> 1) * 8;
                    if (col == row) DG[ti * 128 + row] = e;
                }
            }
        }
    }

    // row reduce across the quad (lanes sharing rows, differing cols)
    #pragma unroll
    for (int mt = 0; mt < 2; mt++)
        #pragma unroll
        for (int h = 0; h < 2; h++) {
            float v = rsum[mt][h];
            v += __shfl_xor_sync(0xFFFFFFFF, v, 1);
            v += __shfl_xor_sync(0xFFFFFFFF, v, 2);
            rsum[mt][h] = v;
        }
    if (qp == 0) {
        #pragma unroll
        for (int mt = 0; mt < 2; mt++)
            #pragma unroll
            for (int h = 0; h < 2; h++) {
                int row = ti * 128 + wm * 32 + mt * 16 + qr + h * 8;
                atomicAdd(&RS[row], rsum[mt][h]);
            }
    }

    if (docol) {
        // col reduce across qr (lanes 4,8,16 apart share cols, differing rows)
        #pragma unroll
        for (int nt = 0; nt < 8; nt++)
            #pragma unroll
            for (int b = 0; b < 2; b++) {
                float v = csum[nt][b];
                v += __shfl_xor_sync(0xFFFFFFFF, v, 4);
                v += __shfl_xor_sync(0xFFFFFFFF, v, 8);
                v += __shfl_xor_sync(0xFFFFFFFF, v, 16);
                csum[nt][b] = v;
            }
        if (qr == 0) {
            #pragma unroll
            for (int nt = 0; nt < 8; nt++)
                #pragma unroll
                for (int b = 0; b < 2; b++) {
                    int col = tj * 128 + wn * 64 + nt * 8 + qp * 2 + b;
                    atomicAdd(&CS[col], csum[nt][b]);
                }
        }
    }
}

// ---------------- final loss reduction ----------------
__global__ void k_loss(const float* __restrict__ rs11, const float* __restrict__ d11,
                       const float* __restrict__ rs22, const float* __restrict__ d22,
                       const float* __restrict__ rs12, const float* __restrict__ cs12,
                       const float* __restrict__ d12, float* __restrict__ out)
{
    __shared__ float red[256];
    int tid = threadIdx.x;
    float s = 0.f;
    for (int i = tid; i < NN; i += 256) {
        float ld = logf(d12[i]);
        float l1 = logf(rs11[i] + rs12[i] - d11[i]) - ld;
        float l2 = logf(rs22[i] + cs12[i] - d22[i]) - ld;
        s += 0.5f * (l1 + l2);
    }
    red[tid] = s;
    __syncthreads();
    for (int st = 128; st; st >>= 1) {
        if (tid < st) red[tid] += red[tid + st];
        __syncthreads();
    }
    if (tid == 0) out[0] = red[0] / (float)NN;
}

// ---------------- launch ----------------
extern "C" void kernel_launch(void* const* d_in, const int* in_sizes, int n_in,
                              void* d_out, int out_size)
{
    const float* feat[2] = {(const float*)d_in[0], (const float*)d_in[1]};
    const int*   ei[2]   = {(const int*)d_in[2], (const int*)d_in[4]};
    const float* ew[2]   = {(const float*)d_in[3], (const float*)d_in[5]};
    const float* w_l1a = (const float*)d_in[6];
    const float* b_l1a = (const float*)d_in[7];
    const float* w_l1b = (const float*)d_in[8];
    const float* b_l1b = (const float*)d_in[9];
    const float* w_g1  = (const float*)d_in[10];
    const float* b_g1  = (const float*)d_in[11];
    const float* w_g2  = (const float*)d_in[12];
    const float* b_g2  = (const float*)d_in[13];
    const float* w_fc1 = (const float*)d_in[14];
    const float* b_fc1 = (const float*)d_in[15];
    const float* w_fc2 = (const float*)d_in[16];
    const float* b_fc2 = (const float*)d_in[17];
    int E = in_sizes[3];

    float *X, *S1, *G1, *S2, *G2;
    __nv_bfloat16 *Zb1, *Zb2;
    float *rs11, *rs22, *rs12, *cs12, *d11, *d22, *d12;
    int *cnt, *cur, *rowstart, *eidx;
    cudaGetSymbolAddress((void**)&X,  g_X);
    cudaGetSymbolAddress((void**)&S1, g_S1);
    cudaGetSymbolAddress((void**)&G1, g_G1);
    cudaGetSymbolAddress((void**)&S2, g_S2);
    cudaGetSymbolAddress((void**)&G2, g_G2);
    cudaGetSymbolAddress((void**)&Zb1, g_Zb1);
    cudaGetSymbolAddress((void**)&Zb2, g_Zb2);
    cudaGetSymbolAddress((void**)&rs11, g_rs11);
    cudaGetSymbolAddress((void**)&rs22, g_rs22);
    cudaGetSymbolAddress((void**)&rs12, g_rs12);
    cudaGetSymbolAddress((void**)&cs12, g_cs12);
    cudaGetSymbolAddress((void**)&d11, g_d11);
    cudaGetSymbolAddress((void**)&d22, g_d22);
    cudaGetSymbolAddress((void**)&d12, g_d12);
    cudaGetSymbolAddress((void**)&cnt, g_cnt);
    cudaGetSymbolAddress((void**)&cur, g_cur);
    cudaGetSymbolAddress((void**)&rowstart, g_rowstart);
    cudaGetSymbolAddress((void**)&eidx, g_eidx);

    const int PAIR_SMEM = 2 * 128 * LDS_PAIR * 2;   // 69632
    cudaFuncSetAttribute(k_pair_mma, cudaFuncAttributeMaxDynamicSharedMemorySize, PAIR_SMEM);

    int eg = (E + 255) / 256;

    for (int v = 0; v < 2; v++) {
        __nv_bfloat16* Zv = v ? Zb2 : Zb1;
        int* rsv = rowstart + v * (NN + 1);
        int* exv = eidx + v * EMAX;

        // CSR build for graph v
        k_zcnt<<<NN / 256, 256>>>(cnt);
        k_hist<<<eg, 256>>>(ei[v], cnt, E);
        k_scan<<<1, 1024>>>(cnt, rsv, cur);
        k_fill<<<eg, 256>>>(ei[v], cur, exv, E);

        k_mlp   <<<NN / 4, 64>>>(feat[v], w_l1a, b_l1a, w_l1b, b_l1b, X);
        k_sup1  <<<NN, 256>>>(X, w_g1, S1);
        k_gather<<<NN, CHID>>>(rsv, exv, ei[v], ew[v], S1, b_g1, G1, E, CHID);
        k_sup2  <<<NN / 4, 128>>>(G1, w_g2, S2);
        k_gather<<<NN, CACT>>>(rsv, exv, ei[v], ew[v], S2, b_g2, G2, E, CACT);
        k_proj  <<<NN, 128>>>(G2, w_fc1, b_fc1, w_fc2, b_fc2, Zv);
    }

    k_zero4<<<NN / 256, 256>>>(rs11, rs22, rs12, cs12);

    dim3 gp(64, 64, 3);
    k_pair_mma<<<gp, 256, PAIR_SMEM>>>(Zb1, Zb2, rs11, d11, rs22, d22, rs12, d12, cs12);

    k_loss<<<1, 256>>>(rs11, d11, rs22, d22, rs12, cs12, d12, (float*)d_out);
}

// round 13
// speedup vs baseline: 1.4873x; 1.4873x over previous
#include <cuda_runtime.h>
#include <cuda_bf16.h>
#include <math.h>
#include <stdint.h>

#define NN 8192
#define CHID 256
#define CACT 128
#define EMAX 262144

// ---------------- scratch (no allocations allowed) ----------------
__device__ float g_X [NN * 32];
__device__ float g_S1[NN * CHID];
__device__ float g_G1[NN * CHID];
__device__ float g_S2[NN * CACT];
__device__ float g_G2[NN * CACT];
__device__ __align__(16) __nv_bfloat16 g_Zb1[NN * CACT];
__device__ __align__(16) __nv_bfloat16 g_Zb2[NN * CACT];
__device__ float g_rs11[NN], g_rs22[NN], g_rs12[NN], g_cs12[NN];
__device__ float g_d11[NN], g_d22[NN], g_d12[NN];
__device__ int g_cnt[NN];
__device__ int g_cur[NN];
__device__ int g_rowstart[2 * (NN + 1)];
__device__ int g_eidx[2 * EMAX];

// ================= warp-MMA helpers (sm_80+ PTX, safe for compute_103) =================
__device__ __forceinline__ uint32_t smem_u32(const void* p) {
    uint32_t a;
    asm("{ .reg .u64 t; cvta.to.shared.u64 t, %1; cvt.u32.u64 %0, t; }" : "=r"(a) : "l"(p));
    return a;
}
__device__ __forceinline__ void ldsm_x4(uint32_t& r0, uint32_t& r1, uint32_t& r2, uint32_t& r3,
                                        uint32_t saddr) {
    asm volatile("ldmatrix.sync.aligned.m8n8.x4.shared.b16 {%0,%1,%2,%3}, [%4];"
                 : "=r"(r0), "=r"(r1), "=r"(r2), "=r"(r3) : "r"(saddr));
}
__device__ __forceinline__ void mma16816(float* c, uint32_t a0, uint32_t a1, uint32_t a2,
                                         uint32_t a3, uint32_t b0, uint32_t b1) {
    asm volatile(
        "mma.sync.aligned.m16n8k16.row.col.f32.bf16.bf16.f32 "
        "{%0,%1,%2,%3}, {%4,%5,%6,%7}, {%8,%9}, {%0,%1,%2,%3};"
        : "+f"(c[0]), "+f"(c[1]), "+f"(c[2]), "+f"(c[3])
        : "r"(a0), "r"(a1), "r"(a2), "r"(a3), "r"(b0), "r"(b1));
}

// ---------------- MLP: x = relu(feat@w1+b1)@w2+b2  (512->64->32), 4 rows/block ----------------
__global__ void k_mlp(const float* __restrict__ feat,
                      const float* __restrict__ w1, const float* __restrict__ b1,
                      const float* __restrict__ w2, const float* __restrict__ b2,
                      float* __restrict__ xout)
{
    __shared__ float sf[4 * 512];
    __shared__ float t1[4][64];
    int tid = threadIdx.x;           // 64 threads
    int r0 = blockIdx.x * 4;
    const float4* f4 = (const float4*)(feat + (size_t)r0 * 512);
    #pragma unroll
    for (int i = 0; i < 8; i++)
        ((float4*)sf)[tid + i * 64] = f4[tid + i * 64];
    __syncthreads();
    float a0 = b1[tid], a1 = a0, a2 = a0, a3 = a0;
    #pragma unroll 4
    for (int k = 0; k < 512; k++) {
        float wv = w1[k * 64 + tid];
        a0 = fmaf(sf[k], wv, a0);
        a1 = fmaf(sf[512 + k], wv, a1);
        a2 = fmaf(sf[1024 + k], wv, a2);
        a3 = fmaf(sf[1536 + k], wv, a3);
    }
    t1[0][tid] = fmaxf(a0, 0.f); t1[1][tid] = fmaxf(a1, 0.f);
    t1[2][tid] = fmaxf(a2, 0.f); t1[3][tid] = fmaxf(a3, 0.f);
    __syncthreads();
    #pragma unroll
    for (int t = tid; t < 128; t += 64) {
        int r = t >> 5, o = t & 31;
        float acc = b2[o];
        #pragma unroll
        for (int k = 0; k < 64; k++)
            acc = fmaf(t1[r][k], w2[k * 32 + o], acc);
        xout[(r0 + r) * 32 + o] = acc;
    }
}

// ---------------- support1 = x @ w_g1  (32 -> 256), one row/block ----------------
__global__ void k_sup1(const float* __restrict__ x, const float* __restrict__ w,
                       float* __restrict__ sup)
{
    __shared__ float sx[32];
    int tid = threadIdx.x;           // 256
    int row = blockIdx.x;
    if (tid < 32) sx[tid] = x[row * 32 + tid];
    __syncthreads();
    float acc = 0.f;
    #pragma unroll
    for (int k = 0; k < 32; k++)
        acc = fmaf(sx[k], w[k * 256 + tid], acc);
    sup[row * 256 + tid] = acc;
}

// ---------------- CSR build ----------------
__global__ void k_zcnt(int* __restrict__ cnt)
{
    int i = blockIdx.x * blockDim.x + threadIdx.x;
    if (i < NN) cnt[i] = 0;
}
__global__ void k_hist(const int* __restrict__ ei, int* __restrict__ cnt, int E)
{
    int e = blockIdx.x * blockDim.x + threadIdx.x;
    if (e < E) atomicAdd(&cnt[ei[e]], 1);
}
__global__ void k_scan(const int* __restrict__ cnt, int* __restrict__ rowstart,
                       int* __restrict__ cur)
{
    __shared__ int ps[1024];
    int t = threadIdx.x;             // 1024 threads
    int loc[8]; int s = 0;
    #pragma unroll
    for (int j = 0; j < 8; j++) { loc[j] = s; s += cnt[t * 8 + j]; }
    ps[t] = s;
    __syncthreads();
    for (int off = 1; off < 1024; off <<= 1) {
        int v = (t >= off) ? ps[t - off] : 0;
        __syncthreads();
        ps[t] += v;
        __syncthreads();
    }
    int b = ps[t] - s;               // exclusive base
    #pragma unroll
    for (int j = 0; j < 8; j++) { rowstart[t * 8 + j] = b + loc[j]; cur[t * 8 + j] = b + loc[j]; }
    if (t == 1023) rowstart[NN] = ps[1023];
}
__global__ void k_fill(const int* __restrict__ ei, int* __restrict__ cur,
                       int* __restrict__ eidx, int E)
{
    int e = blockIdx.x * blockDim.x + threadIdx.x;
    if (e >= E) return;
    int p = atomicAdd(&cur[ei[e]], 1);
    eidx[p] = e;
}

// ---------------- CSR gather: out[r][c] = b[c] + sum_e w_e * sup[src_e][c] ----------------
__global__ void k_gather(const int* __restrict__ rowstart, const int* __restrict__ eidx,
                         const int* __restrict__ ei, const float* __restrict__ ew,
                         const float* __restrict__ sup, const float* __restrict__ bias,
                         float* __restrict__ out, int E, int C)
{
    __shared__ int ssrc[128];
    __shared__ float swt[128];
    int r = blockIdx.x, c = threadIdx.x;     // C threads
    int s0 = rowstart[r], s1 = rowstart[r + 1];
    float acc = bias[c];
    for (int base = s0; base < s1; base += 128) {
        int len = min(128, s1 - base);
        __syncthreads();
        if (c < len) {
            int e = eidx[base + c];
            ssrc[c] = ei[E + e];
            swt[c]  = ew[e];
        }
        __syncthreads();
        for (int i = 0; i < len; i++)
            acc = fmaf(swt[i], sup[(size_t)ssrc[i] * C + c], acc);
    }
    out[(size_t)r * C + c] = acc;
}

// ---------------- support2 = relu(h) @ w_g2  (256 -> 128), 4 rows/block ----------------
__global__ void k_sup2(const float* __restrict__ h, const float* __restrict__ w,
                       float* __restrict__ sup)
{
    __shared__ float sh[4 * 256];
    int tid = threadIdx.x;           // 128
    int r0 = blockIdx.x * 4;
    #pragma unroll
    for (int i = tid; i < 1024; i += 128)
        sh[i] = fmaxf(h[(size_t)r0 * 256 + i], 0.f);
    __syncthreads();
    float a0 = 0, a1 = 0, a2 = 0, a3 = 0;
    #pragma unroll 4
    for (int k = 0; k < 256; k++) {
        float wv = w[k * 128 + tid];
        a0 = fmaf(sh[k], wv, a0);
        a1 = fmaf(sh[256 + k], wv, a1);
        a2 = fmaf(sh[512 + k], wv, a2);
        a3 = fmaf(sh[768 + k], wv, a3);
    }
    sup[(r0 + 0) * 128 + tid] = a0;
    sup[(r0 + 1) * 128 + tid] = a1;
    sup[(r0 + 2) * 128 + tid] = a2;
    sup[(r0 + 3) * 128 + tid] = a3;
}

// ---------------- proj + L2 normalize -> bf16 ----------------
__global__ void k_proj(const float* __restrict__ h,
                       const float* __restrict__ w1, const float* __restrict__ b1,
                       const float* __restrict__ w2, const float* __restrict__ b2,
                       __nv_bfloat16* __restrict__ zb)
{
    __shared__ float sh[128];
    __shared__ float t[64];
    __shared__ float red[128];
    int tid = threadIdx.x;           // 128
    int row = blockIdx.x;
    sh[tid] = h[row * 128 + tid];
    __syncthreads();
    if (tid < 64) {
        float a = b1[tid];
        #pragma unroll
        for (int k = 0; k < 128; k++)
            a = fmaf(sh[k], w1[k * 64 + tid], a);
        t[tid] = a > 0.f ? a : expm1f(a);
    }
    __syncthreads();
    float a = b2[tid];
    #pragma unroll
    for (int k = 0; k < 64; k++)
        a = fmaf(t[k], w2[k * 128 + tid], a);
    red[tid] = a * a;
    __syncthreads();
    for (int st = 64; st; st >>= 1) {
        if (tid < st) red[tid] += red[tid + st];
        __syncthreads();
    }
    float inv = 1.f / fmaxf(sqrtf(red[0]), 1e-12f);
    zb[row * 128 + tid] = __float2bfloat16(a * inv);
}

// ---------------- zero accumulators ----------------
__global__ void k_zero4(float* a, float* b, float* c, float* d)
{
    int i = blockIdx.x * blockDim.x + threadIdx.x;
    if (i < NN) { a[i] = 0.f; b[i] = 0.f; c[i] = 0.f; d[i] = 0.f; }
}

// ---------------- bf16 HMMA pairwise exp row/col-sums (symmetry-reduced) ----------------
// job0: Z1 Z1^T (sym, tj>=ti) -> rs11 (+d11). off-diag col sums feed rows of tj block.
// job1: Z2 Z2^T (sym, tj>=ti) -> rs22 (+d22). same.
// job2: Z1 Z2^T (full)        -> row sums rs12 (+d12), col sums cs12.
// Block: 128x128 tile, 256 threads = 8 warps (4M x 2N), warp tile 32x64.
// Epilogue is nt-outer so column partials live in 2 registers, keeping the
// kernel at <=128 regs (2 blocks/SM) — forced via __launch_bounds__(256,2).
#define LDS_PAIR 136
__global__ void __launch_bounds__(256, 2) k_pair_mma(
    const __nv_bfloat16* __restrict__ Zb1, const __nv_bfloat16* __restrict__ Zb2,
    float* __restrict__ rs11, float* __restrict__ d11,
    float* __restrict__ rs22, float* __restrict__ d22,
    float* __restrict__ rs12, float* __restrict__ d12,
    float* __restrict__ cs12)
{
    int job = blockIdx.z, ti = blockIdx.y, tj = blockIdx.x;
    bool sym = (job < 2);
    if (sym && tj < ti) return;

    extern __shared__ __nv_bfloat16 smp[];
    __nv_bfloat16* As = smp;                       // 128 x 136
    __nv_bfloat16* Bs = smp + 128 * LDS_PAIR;      // 128 x 136

    int tid = threadIdx.x, wid = tid >> 5, lane = tid & 31;
    int wm = wid >> 1, wn = wid & 1;               // warp grid 4x2

    const __nv_bfloat16* A = (job == 1) ? Zb2 : Zb1;
    const __nv_bfloat16* B = (job == 0) ? Zb1 : Zb2;
    float* RS = (job == 0) ? rs11 : (job == 1) ? rs22 : rs12;
    float* CS = (job == 0) ? rs11 : (job == 1) ? rs22 : cs12;
    float* DG = (job == 0) ? d11 : (job == 1) ? d22 : d12;
    bool dtile = (ti == tj);
    bool docol = (job == 2) || (tj > ti);

    // load 128x128 bf16 tiles (uint4 = 8 bf16 per thread-iter)
    const __nv_bfloat16* Ap = A + (size_t)ti * 128 * 128;
    const __nv_bfloat16* Bp = B + (size_t)tj * 128 * 128;
    #pragma unroll
    for (int it = 0; it < 8; it++) {
        int idx = it * 256 + tid;
        int row = idx >> 4, col8 = (idx & 15) * 8;
        *(uint4*)(As + row * LDS_PAIR + col8) = *(const uint4*)(Ap + (size_t)row * 128 + col8);
        *(uint4*)(Bs + row * LDS_PAIR + col8) = *(const uint4*)(Bp + (size_t)row * 128 + col8);
    }
    __syncthreads();

    float acc[2][8][4];
    #pragma unroll
    for (int mt = 0; mt < 2; mt++)
        #pragma unroll
        for (int nt = 0; nt < 8; nt++)
            #pragma unroll
            for (int q = 0; q < 4; q++) acc[mt][nt][q] = 0.f;

    uint32_t a_base = smem_u32(As);
    uint32_t b_base = smem_u32(Bs);
    int lrow = lane & 15, lcol = (lane >> 4) * 8;

    #pragma unroll
    for (int ks = 0; ks < 8; ks++) {
        int k0 = ks * 16;
        uint32_t af[2][4];
        #pragma unroll
        for (int mt = 0; mt < 2; mt++) {
            uint32_t addr = a_base + ((wm * 32 + mt * 16 + lrow) * LDS_PAIR + k0 + lcol) * 2;
            ldsm_x4(af[mt][0], af[mt][1], af[mt][2], af[mt][3], addr);
        }
        uint32_t bf[8][2];
        #pragma unroll
        for (int p = 0; p < 4; p++) {
            uint32_t r0, r1, r2, r3;
            uint32_t addr = b_base + ((wn * 64 + p * 16 + lrow) * LDS_PAIR + k0 + lcol) * 2;
            ldsm_x4(r0, r1, r2, r3, addr);
            bf[2 * p][0] = r0; bf[2 * p][1] = r2;
            bf[2 * p + 1][0] = r1; bf[2 * p + 1][1] = r3;
        }
        #pragma unroll
        for (int mt = 0; mt < 2; mt++)
            #pragma unroll
            for (int nt = 0; nt < 8; nt++)
                mma16816(acc[mt][nt], af[mt][0], af[mt][1], af[mt][2], af[mt][3],
                         bf[nt][0], bf[nt][1]);
    }

    // Epilogue, nt-outer to keep register pressure low:
    //   e = exp(2*s); row partials persist (4 regs); col partials are per-nt
    //   (2 regs) and flushed via shfl+atomic inside the nt loop.
    int qp = lane & 3, qr = lane >> 2;
    float rsum[2][2] = {{0.f, 0.f}, {0.f, 0.f}};

    #pragma unroll
    for (int nt = 0; nt < 8; nt++) {
        float c0 = 0.f, c1 = 0.f;
        #pragma unroll
        for (int mt = 0; mt < 2; mt++) {
            #pragma unroll
            for (int q = 0; q < 4; q++) {
                float e = __expf(2.0f * acc[mt][nt][q]);   // 1/TEMP = 2
                rsum[mt][q >> 1] += e;
                if (q & 1) c1 += e; else c0 += e;
                if (dtile) {
                    int col = wn * 64 + nt * 8 + qp * 2 + (q & 1);
                    int row = wm * 32 + mt * 16 + qr + (q >> 1) * 8;
                    if (col == row) DG[ti * 128 + row] = e;
                }
            }
        }
        if (docol) {
            #pragma unroll
            for (int sh = 4; sh <= 16; sh <<= 1) {
                c0 += __shfl_xor_sync(0xFFFFFFFF, c0, sh);
                c1 += __shfl_xor_sync(0xFFFFFFFF, c1, sh);
            }
            if (qr == 0) {
                int col = tj * 128 + wn * 64 + nt * 8 + qp * 2;
                atomicAdd(&CS[col], c0);
                atomicAdd(&CS[col + 1], c1);
            }
        }
    }

    // row reduce across the quad (lanes sharing rows, differing cols)
    #pragma unroll
    for (int mt = 0; mt < 2; mt++)
        #pragma unroll
        for (int h = 0; h < 2; h++) {
            float v = rsum[mt][h];
            v += __shfl_xor_sync(0xFFFFFFFF, v, 1);
            v += __shfl_xor_sync(0xFFFFFFFF, v, 2);
            if (qp == 0) {
                int row = ti * 128 + wm * 32 + mt * 16 + qr + h * 8;
                atomicAdd(&RS[row], v);
            }
        }
}

// ---------------- final loss reduction ----------------
__global__ void k_loss(const float* __restrict__ rs11, const float* __restrict__ d11,
                       const float* __restrict__ rs22, const float* __restrict__ d22,
                       const float* __restrict__ rs12, const float* __restrict__ cs12,
                       const float* __restrict__ d12, float* __restrict__ out)
{
    __shared__ float red[256];
    int tid = threadIdx.x;
    float s = 0.f;
    for (int i = tid; i < NN; i += 256) {
        float ld = logf(d12[i]);
        float l1 = logf(rs11[i] + rs12[i] - d11[i]) - ld;
        float l2 = logf(rs22[i] + cs12[i] - d22[i]) - ld;
        s += 0.5f * (l1 + l2);
    }
    red[tid] = s;
    __syncthreads();
    for (int st = 128; st; st >>= 1) {
        if (tid < st) red[tid] += red[tid + st];
        __syncthreads();
    }
    if (tid == 0) out[0] = red[0] / (float)NN;
}

// ---------------- launch ----------------
extern "C" void kernel_launch(void* const* d_in, const int* in_sizes, int n_in,
                              void* d_out, int out_size)
{
    const float* feat[2] = {(const float*)d_in[0], (const float*)d_in[1]};
    const int*   ei[2]   = {(const int*)d_in[2], (const int*)d_in[4]};
    const float* ew[2]   = {(const float*)d_in[3], (const float*)d_in[5]};
    const float* w_l1a = (const float*)d_in[6];
    const float* b_l1a = (const float*)d_in[7];
    const float* w_l1b = (const float*)d_in[8];
    const float* b_l1b = (const float*)d_in[9];
    const float* w_g1  = (const float*)d_in[10];
    const float* b_g1  = (const float*)d_in[11];
    const float* w_g2  = (const float*)d_in[12];
    const float* b_g2  = (const float*)d_in[13];
    const float* w_fc1 = (const float*)d_in[14];
    const float* b_fc1 = (const float*)d_in[15];
    const float* w_fc2 = (const float*)d_in[16];
    const float* b_fc2 = (const float*)d_in[17];
    int E = in_sizes[3];

    float *X, *S1, *G1, *S2, *G2;
    __nv_bfloat16 *Zb1, *Zb2;
    float *rs11, *rs22, *rs12, *cs12, *d11, *d22, *d12;
    int *cnt, *cur, *rowstart, *eidx;
    cudaGetSymbolAddress((void**)&X,  g_X);
    cudaGetSymbolAddress((void**)&S1, g_S1);
    cudaGetSymbolAddress((void**)&G1, g_G1);
    cudaGetSymbolAddress((void**)&S2, g_S2);
    cudaGetSymbolAddress((void**)&G2, g_G2);
    cudaGetSymbolAddress((void**)&Zb1, g_Zb1);
    cudaGetSymbolAddress((void**)&Zb2, g_Zb2);
    cudaGetSymbolAddress((void**)&rs11, g_rs11);
    cudaGetSymbolAddress((void**)&rs22, g_rs22);
    cudaGetSymbolAddress((void**)&rs12, g_rs12);
    cudaGetSymbolAddress((void**)&cs12, g_cs12);
    cudaGetSymbolAddress((void**)&d11, g_d11);
    cudaGetSymbolAddress((void**)&d22, g_d22);
    cudaGetSymbolAddress((void**)&d12, g_d12);
    cudaGetSymbolAddress((void**)&cnt, g_cnt);
    cudaGetSymbolAddress((void**)&cur, g_cur);
    cudaGetSymbolAddress((void**)&rowstart, g_rowstart);
    cudaGetSymbolAddress((void**)&eidx, g_eidx);

    const int PAIR_SMEM = 2 * 128 * LDS_PAIR * 2;   // 69632
    cudaFuncSetAttribute(k_pair_mma, cudaFuncAttributeMaxDynamicSharedMemorySize, PAIR_SMEM);

    int eg = (E + 255) / 256;

    for (int v = 0; v < 2; v++) {
        __nv_bfloat16* Zv = v ? Zb2 : Zb1;
        int* rsv = rowstart + v * (NN + 1);
        int* exv = eidx + v * EMAX;

        // CSR build for graph v
        k_zcnt<<<NN / 256, 256>>>(cnt);
        k_hist<<<eg, 256>>>(ei[v], cnt, E);
        k_scan<<<1, 1024>>>(cnt, rsv, cur);
        k_fill<<<eg, 256>>>(ei[v], cur, exv, E);

        k_mlp   <<<NN / 4, 64>>>(feat[v], w_l1a, b_l1a, w_l1b, b_l1b, X);
        k_sup1  <<<NN, 256>>>(X, w_g1, S1);
        k_gather<<<NN, CHID>>>(rsv, exv, ei[v], ew[v], S1, b_g1, G1, E, CHID);
        k_sup2  <<<NN / 4, 128>>>(G1, w_g2, S2);
        k_gather<<<NN, CACT>>>(rsv, exv, ei[v], ew[v], S2, b_g2, G2, E, CACT);
        k_proj  <<<NN, 128>>>(G2, w_fc1, b_fc1, w_fc2, b_fc2, Zv);
    }

    k_zero4<<<NN / 256, 256>>>(rs11, rs22, rs12, cs12);

    dim3 gp(64, 64, 3);
    k_pair_mma<<<gp, 256, PAIR_SMEM>>>(Zb1, Zb2, rs11, d11, rs22, d22, rs12, d12, cs12);

    k_loss<<<1, 256>>>(rs11, d11, rs22, d22, rs12, cs12, d12, (float*)d_out);
}

// round 14
// speedup vs baseline: 1.5115x; 1.0163x over previous
#include <cuda_runtime.h>
#include <cuda_bf16.h>
#include <math.h>
#include <stdint.h>

#define NN 8192
#define CHID 256
#define CACT 128
#define EMAX 262144

// ---------------- scratch (no allocations allowed) ----------------
__device__ float g_X [2 * NN * 32];
__device__ float g_S1[2 * NN * CHID];
__device__ float g_G1[2 * NN * CHID];
__device__ float g_S2[2 * NN * CACT];
__device__ float g_G2[2 * NN * CACT];
__device__ __align__(16) __nv_bfloat16 g_Zb1[NN * CACT];
__device__ __align__(16) __nv_bfloat16 g_Zb2[NN * CACT];
__device__ float g_rs11[NN], g_rs22[NN], g_rs12[NN], g_cs12[NN];
__device__ float g_d11[NN], g_d22[NN], g_d12[NN];
__device__ int g_cnt[2 * NN];
__device__ int g_cur[2 * NN];
__device__ int g_rowstart[2 * (NN + 1)];
__device__ int g_eidx[2 * EMAX];

// ================= warp-MMA helpers (sm_80+ PTX, safe for compute_103) =================
__device__ __forceinline__ uint32_t smem_u32(const void* p) {
    uint32_t a;
    asm("{ .reg .u64 t; cvta.to.shared.u64 t, %1; cvt.u32.u64 %0, t; }" : "=r"(a) : "l"(p));
    return a;
}
__device__ __forceinline__ void ldsm_x4(uint32_t& r0, uint32_t& r1, uint32_t& r2, uint32_t& r3,
                                        uint32_t saddr) {
    asm volatile("ldmatrix.sync.aligned.m8n8.x4.shared.b16 {%0,%1,%2,%3}, [%4];"
                 : "=r"(r0), "=r"(r1), "=r"(r2), "=r"(r3) : "r"(saddr));
}
__device__ __forceinline__ void mma16816(float* c, uint32_t a0, uint32_t a1, uint32_t a2,
                                         uint32_t a3, uint32_t b0, uint32_t b1) {
    asm volatile(
        "mma.sync.aligned.m16n8k16.row.col.f32.bf16.bf16.f32 "
        "{%0,%1,%2,%3}, {%4,%5,%6,%7}, {%8,%9}, {%0,%1,%2,%3};"
        : "+f"(c[0]), "+f"(c[1]), "+f"(c[2]), "+f"(c[3])
        : "r"(a0), "r"(a1), "r"(a2), "r"(a3), "r"(b0), "r"(b1));
}

// ---------------- MLP both views: x = relu(feat@w1+b1)@w2+b2  (512->64->32) ----------------
// 256 threads, 16 rows/block, grid (NN/16, 2)
__global__ void k_mlp2(const float* __restrict__ f1, const float* __restrict__ f2,
                       const float* __restrict__ w1, const float* __restrict__ b1,
                       const float* __restrict__ w2, const float* __restrict__ b2,
                       float* __restrict__ xout)
{
    __shared__ float sf[16 * 512];   // 32KB
    __shared__ float t1[16 * 64];    // 4KB
    int tid = threadIdx.x;
    int v = blockIdx.y;
    const float* feat = v ? f2 : f1;
    int r0 = blockIdx.x * 16;
    const float4* f4 = (const float4*)(feat + (size_t)r0 * 512);
    #pragma unroll
    for (int i = 0; i < 8; i++)
        ((float4*)sf)[tid + i * 256] = f4[tid + i * 256];
    __syncthreads();

    int col = tid & 63, rg = tid >> 6;            // 4 row-groups of 4 rows
    {
        float b = b1[col];
        float a0 = b, a1 = b, a2 = b, a3 = b;
        const float* s0 = sf + (rg * 4 + 0) * 512;
        const float* s1 = sf + (rg * 4 + 1) * 512;
        const float* s2 = sf + (rg * 4 + 2) * 512;
        const float* s3 = sf + (rg * 4 + 3) * 512;
        #pragma unroll 4
        for (int k = 0; k < 512; k++) {
            float wv = w1[k * 64 + col];
            a0 = fmaf(s0[k], wv, a0);
            a1 = fmaf(s1[k], wv, a1);
            a2 = fmaf(s2[k], wv, a2);
            a3 = fmaf(s3[k], wv, a3);
        }
        t1[(rg * 4 + 0) * 64 + col] = fmaxf(a0, 0.f);
        t1[(rg * 4 + 1) * 64 + col] = fmaxf(a1, 0.f);
        t1[(rg * 4 + 2) * 64 + col] = fmaxf(a2, 0.f);
        t1[(rg * 4 + 3) * 64 + col] = fmaxf(a3, 0.f);
    }
    __syncthreads();

    float* xo = xout + (size_t)v * NN * 32;
    #pragma unroll
    for (int o = tid; o < 512; o += 256) {
        int r = o >> 5, c = o & 31;
        float acc = b2[c];
        #pragma unroll
        for (int k = 0; k < 64; k++)
            acc = fmaf(t1[r * 64 + k], w2[k * 32 + c], acc);
        xo[(r0 + r) * 32 + c] = acc;
    }
}

// ---------------- support1 both views: sup = x @ w_g1 (32->256), 16 rows/block ----------------
__global__ void k_sup1_2(const float* __restrict__ x, const float* __restrict__ w,
                         float* __restrict__ sup)
{
    __shared__ float sx[16 * 32];    // 2KB
    int tid = threadIdx.x;           // 256
    int v = blockIdx.y;
    int r0 = blockIdx.x * 16;
    const float* xv = x + (size_t)v * NN * 32 + (size_t)r0 * 32;
    sx[tid] = xv[tid];
    sx[tid + 256] = xv[tid + 256];
    __syncthreads();

    float accs[16];
    #pragma unroll
    for (int r = 0; r < 16; r++) accs[r] = 0.f;
    #pragma unroll 4
    for (int k = 0; k < 32; k++) {
        float wv = w[k * 256 + tid];
        #pragma unroll
        for (int r = 0; r < 16; r++)
            accs[r] = fmaf(sx[r * 32 + k], wv, accs[r]);
    }
    float* sv = sup + (size_t)v * NN * CHID;
    #pragma unroll
    for (int r = 0; r < 16; r++)
        sv[(size_t)(r0 + r) * 256 + tid] = accs[r];
}

// ---------------- CSR build (both views in each launch) ----------------
__global__ void k_zcnt2(int* __restrict__ cnt)
{
    int i = blockIdx.x * blockDim.x + threadIdx.x;
    if (i < 2 * NN) cnt[i] = 0;
}
__global__ void k_hist2(const int* __restrict__ ei1, const int* __restrict__ ei2,
                        int* __restrict__ cnt, int E)
{
    int e = blockIdx.x * blockDim.x + threadIdx.x;
    int v = blockIdx.y;
    const int* ei = v ? ei2 : ei1;
    if (e < E) atomicAdd(&cnt[v * NN + ei[e]], 1);
}
__global__ void k_scan2(const int* __restrict__ cnt_, int* __restrict__ rowstart_,
                        int* __restrict__ cur_)
{
    __shared__ int ps[1024];
    int b = blockIdx.x;              // view
    const int* cnt = cnt_ + b * NN;
    int* rowstart = rowstart_ + b * (NN + 1);
    int* cur = cur_ + b * NN;
    int t = threadIdx.x;             // 1024 threads
    int loc[8]; int s = 0;
    #pragma unroll
    for (int j = 0; j < 8; j++) { loc[j] = s; s += cnt[t * 8 + j]; }
    ps[t] = s;
    __syncthreads();
    for (int off = 1; off < 1024; off <<= 1) {
        int vv = (t >= off) ? ps[t - off] : 0;
        __syncthreads();
        ps[t] += vv;
        __syncthreads();
    }
    int base = ps[t] - s;            // exclusive base
    #pragma unroll
    for (int j = 0; j < 8; j++) { rowstart[t * 8 + j] = base + loc[j]; cur[t * 8 + j] = base + loc[j]; }
    if (t == 1023) rowstart[NN] = ps[1023];
}
__global__ void k_fill2(const int* __restrict__ ei1, const int* __restrict__ ei2,
                        int* __restrict__ cur, int* __restrict__ eidx, int E)
{
    int e = blockIdx.x * blockDim.x + threadIdx.x;
    int v = blockIdx.y;
    if (e >= E) return;
    const int* ei = v ? ei2 : ei1;
    int p = atomicAdd(&cur[v * NN + ei[e]], 1);
    eidx[v * EMAX + p] = e;
}

// ---------------- CSR gather both views: out[r][c] = b[c] + sum_e w_e*sup[src_e][c] ----------------
__global__ void k_gather2(const int* __restrict__ rowstart_, const int* __restrict__ eidx_,
                          const int* __restrict__ ei1, const float* __restrict__ ew1,
                          const int* __restrict__ ei2, const float* __restrict__ ew2,
                          const float* __restrict__ sup, const float* __restrict__ bias,
                          float* __restrict__ out, int E, int C)
{
    __shared__ int ssrc[128];
    __shared__ float swt[128];
    int v = blockIdx.y;
    const int* ei = v ? ei2 : ei1;
    const float* ew = v ? ew2 : ew1;
    const int* rowstart = rowstart_ + v * (NN + 1);
    const int* eidx = eidx_ + v * EMAX;
    const float* supv = sup + (size_t)v * NN * C;
    float* outv = out + (size_t)v * NN * C;

    int r = blockIdx.x, c = threadIdx.x;     // C threads
    int s0 = rowstart[r], s1 = rowstart[r + 1];
    float acc = bias[c];
    for (int base = s0; base < s1; base += 128) {
        int len = min(128, s1 - base);
        __syncthreads();
        if (c < len) {
            int e = eidx[base + c];
            ssrc[c] = ei[E + e];
            swt[c]  = ew[e];
        }
        __syncthreads();
        float a0 = 0.f, a1 = 0.f, a2 = 0.f, a3 = 0.f;
        int i = 0;
        for (; i + 4 <= len; i += 4) {
            a0 = fmaf(swt[i + 0], supv[(size_t)ssrc[i + 0] * C + c], a0);
            a1 = fmaf(swt[i + 1], supv[(size_t)ssrc[i + 1] * C + c], a1);
            a2 = fmaf(swt[i + 2], supv[(size_t)ssrc[i + 2] * C + c], a2);
            a3 = fmaf(swt[i + 3], supv[(size_t)ssrc[i + 3] * C + c], a3);
        }
        for (; i < len; i++)
            a0 = fmaf(swt[i], supv[(size_t)ssrc[i] * C + c], a0);
        acc += (a0 + a1) + (a2 + a3);
    }
    outv[(size_t)r * C + c] = acc;
}

// ---------------- support2 both views: sup = relu(h) @ w_g2 (256->128), 32 rows/block ----------------
__global__ void k_sup2_2(const float* __restrict__ h, const float* __restrict__ w,
                         float* __restrict__ sup)
{
    __shared__ float sh[32 * 256];   // 32KB
    int tid = threadIdx.x;           // 256
    int v = blockIdx.y;
    int r0 = blockIdx.x * 32;
    const float4* h4 = (const float4*)(h + (size_t)v * NN * CHID + (size_t)r0 * 256);
    #pragma unroll
    for (int i = 0; i < 8; i++) {
        float4 t = h4[tid + i * 256];
        t.x = fmaxf(t.x, 0.f); t.y = fmaxf(t.y, 0.f);
        t.z = fmaxf(t.z, 0.f); t.w = fmaxf(t.w, 0.f);
        ((float4*)sh)[tid + i * 256] = t;
    }
    __syncthreads();

    int col = tid & 127, rg = tid >> 7;          // 2 row-groups of 16 rows
    float accs[16];
    #pragma unroll
    for (int r = 0; r < 16; r++) accs[r] = 0.f;
    const float* shb = sh + rg * 16 * 256;
    #pragma unroll 2
    for (int k = 0; k < 256; k++) {
        float wv = w[k * 128 + col];
        #pragma unroll
        for (int r = 0; r < 16; r++)
            accs[r] = fmaf(shb[r * 256 + k], wv, accs[r]);
    }
    float* sv = sup + (size_t)v * NN * CACT;
    #pragma unroll
    for (int r = 0; r < 16; r++)
        sv[(size_t)(r0 + rg * 16 + r) * 128 + col] = accs[r];
}

// ---------------- proj + L2 normalize -> bf16, both views, 8 rows/block ----------------
__global__ void k_proj2(const float* __restrict__ h,
                        const float* __restrict__ w1, const float* __restrict__ b1,
                        const float* __restrict__ w2, const float* __restrict__ b2,
                        __nv_bfloat16* __restrict__ zb1, __nv_bfloat16* __restrict__ zb2)
{
    __shared__ float sh[8 * 128];    // 4KB
    __shared__ float tt[8 * 64];     // 2KB
    __shared__ float val[8 * 128];   // 4KB
    __shared__ float sinv[8];
    int tid = threadIdx.x;           // 256
    int v = blockIdx.y;
    int r0 = blockIdx.x * 8;
    const float* hv = h + (size_t)v * NN * CACT + (size_t)r0 * 128;
    #pragma unroll
    for (int i = 0; i < 4; i++)
        sh[tid + i * 256] = hv[tid + i * 256];
    __syncthreads();

    // layer1: 8x64 outputs, 2 per thread, ELU
    #pragma unroll
    for (int o = tid; o < 512; o += 256) {
        int r = o >> 6, c = o & 63;
        float a = b1[c];
        #pragma unroll 4
        for (int k = 0; k < 128; k++)
            a = fmaf(sh[r * 128 + k], w1[k * 64 + c], a);
        tt[r * 64 + c] = a > 0.f ? a : expm1f(a);
    }
    __syncthreads();

    // layer2: 8x128 outputs, 4 per thread
    float av[4];
    #pragma unroll
    for (int j = 0; j < 4; j++) {
        int o = tid + j * 256;
        int r = o >> 7, c = o & 127;
        float a = b2[c];
        #pragma unroll
        for (int k = 0; k < 64; k++)
            a = fmaf(tt[r * 64 + k], w2[k * 128 + c], a);
        av[j] = a;
        val[o] = a * a;
    }
    __syncthreads();

    // per-row L2 norm: warp w reduces row w
    int wid = tid >> 5, lane = tid & 31;
    float s = val[wid * 128 + lane] + val[wid * 128 + lane + 32]
            + val[wid * 128 + lane + 64] + val[wid * 128 + lane + 96];
    #pragma unroll
    for (int off = 16; off; off >>= 1)
        s += __shfl_xor_sync(0xFFFFFFFF, s, off);
    if (lane == 0) sinv[wid] = 1.f / fmaxf(sqrtf(s), 1e-12f);
    __syncthreads();

    __nv_bfloat16* zb = v ? zb2 : zb1;
    #pragma unroll
    for (int j = 0; j < 4; j++) {
        int o = tid + j * 256;
        int r = o >> 7, c = o & 127;
        zb[(size_t)(r0 + r) * 128 + c] = __float2bfloat16(av[j] * sinv[r]);
    }
}

// ---------------- zero accumulators ----------------
__global__ void k_zero4(float* a, float* b, float* c, float* d)
{
    int i = blockIdx.x * blockDim.x + threadIdx.x;
    if (i < NN) { a[i] = 0.f; b[i] = 0.f; c[i] = 0.f; d[i] = 0.f; }
}

// ---------------- bf16 HMMA pairwise exp row/col-sums (symmetry-reduced) ----------------
// job0: Z1 Z1^T (sym, tj>=ti) -> rs11 (+d11). off-diag col sums feed rows of tj block.
// job1: Z2 Z2^T (sym, tj>=ti) -> rs22 (+d22). same.
// job2: Z1 Z2^T (full)        -> row sums rs12 (+d12), col sums cs12.
// Block: 128x128 tile, 256 threads = 8 warps (4M x 2N), warp tile 32x64.
#define LDS_PAIR 136
__global__ void __launch_bounds__(256, 2) k_pair_mma(
    const __nv_bfloat16* __restrict__ Zb1, const __nv_bfloat16* __restrict__ Zb2,
    float* __restrict__ rs11, float* __restrict__ d11,
    float* __restrict__ rs22, float* __restrict__ d22,
    float* __restrict__ rs12, float* __restrict__ d12,
    float* __restrict__ cs12)
{
    int job = blockIdx.z, ti = blockIdx.y, tj = blockIdx.x;
    bool sym = (job < 2);
    if (sym && tj < ti) return;

    extern __shared__ __nv_bfloat16 smp[];
    __nv_bfloat16* As = smp;                       // 128 x 136
    __nv_bfloat16* Bs = smp + 128 * LDS_PAIR;      // 128 x 136

    int tid = threadIdx.x, wid = tid >> 5, lane = tid & 31;
    int wm = wid >> 1, wn = wid & 1;               // warp grid 4x2

    const __nv_bfloat16* A = (job == 1) ? Zb2 : Zb1;
    const __nv_bfloat16* B = (job == 0) ? Zb1 : Zb2;
    float* RS = (job == 0) ? rs11 : (job == 1) ? rs22 : rs12;
    float* CS = (job == 0) ? rs11 : (job == 1) ? rs22 : cs12;
    float* DG = (job == 0) ? d11 : (job == 1) ? d22 : d12;
    bool dtile = (ti == tj);
    bool docol = (job == 2) || (tj > ti);

    const __nv_bfloat16* Ap = A + (size_t)ti * 128 * 128;
    const __nv_bfloat16* Bp = B + (size_t)tj * 128 * 128;
    #pragma unroll
    for (int it = 0; it < 8; it++) {
        int idx = it * 256 + tid;
        int row = idx >> 4, col8 = (idx & 15) * 8;
        *(uint4*)(As + row * LDS_PAIR + col8) = *(const uint4*)(Ap + (size_t)row * 128 + col8);
        *(uint4*)(Bs + row * LDS_PAIR + col8) = *(const uint4*)(Bp + (size_t)row * 128 + col8);
    }
    __syncthreads();

    float acc[2][8][4];
    #pragma unroll
    for (int mt = 0; mt < 2; mt++)
        #pragma unroll
        for (int nt = 0; nt < 8; nt++)
            #pragma unroll
            for (int q = 0; q < 4; q++) acc[mt][nt][q] = 0.f;

    uint32_t a_base = smem_u32(As);
    uint32_t b_base = smem_u32(Bs);
    int lrow = lane & 15, lcol = (lane >> 4) * 8;

    #pragma unroll
    for (int ks = 0; ks < 8; ks++) {
        int k0 = ks * 16;
        uint32_t af[2][4];
        #pragma unroll
        for (int mt = 0; mt < 2; mt++) {
            uint32_t addr = a_base + ((wm * 32 + mt * 16 + lrow) * LDS_PAIR + k0 + lcol) * 2;
            ldsm_x4(af[mt][0], af[mt][1], af[mt][2], af[mt][3], addr);
        }
        uint32_t bf[8][2];
        #pragma unroll
        for (int p = 0; p < 4; p++) {
            uint32_t r0, r1, r2, r3;
            uint32_t addr = b_base + ((wn * 64 + p * 16 + lrow) * LDS_PAIR + k0 + lcol) * 2;
            ldsm_x4(r0, r1, r2, r3, addr);
            bf[2 * p][0] = r0; bf[2 * p][1] = r2;
            bf[2 * p + 1][0] = r1; bf[2 * p + 1][1] = r3;
        }
        #pragma unroll
        for (int mt = 0; mt < 2; mt++)
            #pragma unroll
            for (int nt = 0; nt < 8; nt++)
                mma16816(acc[mt][nt], af[mt][0], af[mt][1], af[mt][2], af[mt][3],
                         bf[nt][0], bf[nt][1]);
    }

    // Epilogue, nt-outer to keep register pressure low.
    int qp = lane & 3, qr = lane >> 2;
    float rsum[2][2] = {{0.f, 0.f}, {0.f, 0.f}};

    #pragma unroll
    for (int nt = 0; nt < 8; nt++) {
        float c0 = 0.f, c1 = 0.f;
        #pragma unroll
        for (int mt = 0; mt < 2; mt++) {
            #pragma unroll
            for (int q = 0; q < 4; q++) {
                float e = __expf(2.0f * acc[mt][nt][q]);   // 1/TEMP = 2
                rsum[mt][q >> 1] += e;
                if (q & 1) c1 += e; else c0 += e;
                if (dtile) {
                    int col = wn * 64 + nt * 8 + qp * 2 + (q & 1);
                    int row = wm * 32 + mt * 16 + qr + (q >> 1) * 8;
                    if (col == row) DG[ti * 128 + row] = e;
                }
            }
        }
        if (docol) {
            #pragma unroll
            for (int sh = 4; sh <= 16; sh <<= 1) {
                c0 += __shfl_xor_sync(0xFFFFFFFF, c0, sh);
                c1 += __shfl_xor_sync(0xFFFFFFFF, c1, sh);
            }
            if (qr == 0) {
                int col = tj * 128 + wn * 64 + nt * 8 + qp * 2;
                atomicAdd(&CS[col], c0);
                atomicAdd(&CS[col + 1], c1);
            }
        }
    }

    #pragma unroll
    for (int mt = 0; mt < 2; mt++)
        #pragma unroll
        for (int h = 0; h < 2; h++) {
            float v = rsum[mt][h];
            v += __shfl_xor_sync(0xFFFFFFFF, v, 1);
            v += __shfl_xor_sync(0xFFFFFFFF, v, 2);
            if (qp == 0) {
                int row = ti * 128 + wm * 32 + mt * 16 + qr + h * 8;
                atomicAdd(&RS[row], v);
            }
        }
}

// ---------------- final loss reduction ----------------
__global__ void k_loss(const float* __restrict__ rs11, const float* __restrict__ d11,
                       const float* __restrict__ rs22, const float* __restrict__ d22,
                       const float* __restrict__ rs12, const float* __restrict__ cs12,
                       const float* __restrict__ d12, float* __restrict__ out)
{
    __shared__ float red[256];
    int tid = threadIdx.x;
    float s = 0.f;
    for (int i = tid; i < NN; i += 256) {
        float ld = logf(d12[i]);
        float l1 = logf(rs11[i] + rs12[i] - d11[i]) - ld;
        float l2 = logf(rs22[i] + cs12[i] - d22[i]) - ld;
        s += 0.5f * (l1 + l2);
    }
    red[tid] = s;
    __syncthreads();
    for (int st = 128; st; st >>= 1) {
        if (tid < st) red[tid] += red[tid + st];
        __syncthreads();
    }
    if (tid == 0) out[0] = red[0] / (float)NN;
}

// ---------------- launch ----------------
extern "C" void kernel_launch(void* const* d_in, const int* in_sizes, int n_in,
                              void* d_out, int out_size)
{
    const float* feat1 = (const float*)d_in[0];
    const float* feat2 = (const float*)d_in[1];
    const int*   ei1   = (const int*)d_in[2];
    const float* ew1   = (const float*)d_in[3];
    const int*   ei2   = (const int*)d_in[4];
    const float* ew2   = (const float*)d_in[5];
    const float* w_l1a = (const float*)d_in[6];
    const float* b_l1a = (const float*)d_in[7];
    const float* w_l1b = (const float*)d_in[8];
    const float* b_l1b = (const float*)d_in[9];
    const float* w_g1  = (const float*)d_in[10];
    const float* b_g1  = (const float*)d_in[11];
    const float* w_g2  = (const float*)d_in[12];
    const float* b_g2  = (const float*)d_in[13];
    const float* w_fc1 = (const float*)d_in[14];
    const float* b_fc1 = (const float*)d_in[15];
    const float* w_fc2 = (const float*)d_in[16];
    const float* b_fc2 = (const float*)d_in[17];
    int E = in_sizes[3];

    float *X, *S1, *G1, *S2, *G2;
    __nv_bfloat16 *Zb1, *Zb2;
    float *rs11, *rs22, *rs12, *cs12, *d11, *d22, *d12;
    int *cnt, *cur, *rowstart, *eidx;
    cudaGetSymbolAddress((void**)&X,  g_X);
    cudaGetSymbolAddress((void**)&S1, g_S1);
    cudaGetSymbolAddress((void**)&G1, g_G1);
    cudaGetSymbolAddress((void**)&S2, g_S2);
    cudaGetSymbolAddress((void**)&G2, g_G2);
    cudaGetSymbolAddress((void**)&Zb1, g_Zb1);
    cudaGetSymbolAddress((void**)&Zb2, g_Zb2);
    cudaGetSymbolAddress((void**)&rs11, g_rs11);
    cudaGetSymbolAddress((void**)&rs22, g_rs22);
    cudaGetSymbolAddress((void**)&rs12, g_rs12);
    cudaGetSymbolAddress((void**)&cs12, g_cs12);
    cudaGetSymbolAddress((void**)&d11, g_d11);
    cudaGetSymbolAddress((void**)&d22, g_d22);
    cudaGetSymbolAddress((void**)&d12, g_d12);
    cudaGetSymbolAddress((void**)&cnt, g_cnt);
    cudaGetSymbolAddress((void**)&cur, g_cur);
    cudaGetSymbolAddress((void**)&rowstart, g_rowstart);
    cudaGetSymbolAddress((void**)&eidx, g_eidx);

    const int PAIR_SMEM = 2 * 128 * LDS_PAIR * 2;   // 69632
    cudaFuncSetAttribute(k_pair_mma, cudaFuncAttributeMaxDynamicSharedMemorySize, PAIR_SMEM);

    int eg = (E + 255) / 256;

    // CSR build, both views per launch
    k_zcnt2<<<2 * NN / 256, 256>>>(cnt);
    k_hist2<<<dim3(eg, 2), 256>>>(ei1, ei2, cnt, E);
    k_scan2<<<2, 1024>>>(cnt, rowstart, cur);
    k_fill2<<<dim3(eg, 2), 256>>>(ei1, ei2, cur, eidx, E);

    // encoder, both views per launch
    k_mlp2  <<<dim3(NN / 16, 2), 256>>>(feat1, feat2, w_l1a, b_l1a, w_l1b, b_l1b, X);
    k_sup1_2<<<dim3(NN / 16, 2), 256>>>(X, w_g1, S1);
    k_gather2<<<dim3(NN, 2), CHID>>>(rowstart, eidx, ei1, ew1, ei2, ew2, S1, b_g1, G1, E, CHID);
    k_sup2_2<<<dim3(NN / 32, 2), 256>>>(G1, w_g2, S2);
    k_gather2<<<dim3(NN, 2), CACT>>>(rowstart, eidx, ei1, ew1, ei2, ew2, S2, b_g2, G2, E, CACT);
    k_proj2 <<<dim3(NN / 8, 2), 256>>>(G2, w_fc1, b_fc1, w_fc2, b_fc2, Zb1, Zb2);

    k_zero4<<<NN / 256, 256>>>(rs11, rs22, rs12, cs12);

    dim3 gp(64, 64, 3);
    k_pair_mma<<<gp, 256, PAIR_SMEM>>>(Zb1, Zb2, rs11, d11, rs22, d22, rs12, d12, cs12);

    k_loss<<<1, 256>>>(rs11, d11, rs22, d22, rs12, cs12, d12, (float*)d_out);
}

// round 16
// speedup vs baseline: 1.7027x; 1.1264x over previous
#include <cuda_runtime.h>
#include <cuda_bf16.h>
#include <math.h>
#include <stdint.h>

#define NN 8192
#define CHID 256
#define CACT 128
#define EMAX 262144

// ---------------- scratch (no allocations allowed) ----------------
__device__ float g_X [2 * NN * 32];      // MLP output x, both views
__device__ float g_AX[2 * NN * 32];      // A @ x (32-dim gather result)
__device__ float g_R [2 * NN * CHID];    // relu((AX)@Wg1 + b_g1)
__device__ float g_S2[2 * NN * CACT];    // R @ Wg2
__device__ float g_G2[2 * NN * CACT];    // A @ S2 + b_g2
__device__ __align__(16) __nv_bfloat16 g_Zb1[NN * CACT];
__device__ __align__(16) __nv_bfloat16 g_Zb2[NN * CACT];
__device__ float g_rs11[NN], g_rs22[NN], g_rs12[NN], g_cs12[NN];
__device__ float g_d11[NN], g_d22[NN], g_d12[NN];
__device__ int g_cnt[2 * NN];
__device__ int g_cur[2 * NN];
__device__ int g_rowstart[2 * (NN + 1)];
__device__ int g_eidx[2 * EMAX];

// ================= warp-MMA helpers (sm_80+ PTX, safe for compute_103) =================
__device__ __forceinline__ uint32_t smem_u32(const void* p) {
    uint32_t a;
    asm("{ .reg .u64 t; cvta.to.shared.u64 t, %1; cvt.u32.u64 %0, t; }" : "=r"(a) : "l"(p));
    return a;
}
__device__ __forceinline__ void ldsm_x4(uint32_t& r0, uint32_t& r1, uint32_t& r2, uint32_t& r3,
                                        uint32_t saddr) {
    asm volatile("ldmatrix.sync.aligned.m8n8.x4.shared.b16 {%0,%1,%2,%3}, [%4];"
                 : "=r"(r0), "=r"(r1), "=r"(r2), "=r"(r3) : "r"(saddr));
}
__device__ __forceinline__ void mma16816(float* c, uint32_t a0, uint32_t a1, uint32_t a2,
                                         uint32_t a3, uint32_t b0, uint32_t b1) {
    asm volatile(
        "mma.sync.aligned.m16n8k16.row.col.f32.bf16.bf16.f32 "
        "{%0,%1,%2,%3}, {%4,%5,%6,%7}, {%8,%9}, {%0,%1,%2,%3};"
        : "+f"(c[0]), "+f"(c[1]), "+f"(c[2]), "+f"(c[3])
        : "r"(a0), "r"(a1), "r"(a2), "r"(a3), "r"(b0), "r"(b1));
}

// ---------------- MLP both views: x = relu(feat@w1+b1)@w2+b2  (512->64->32) ----------------
// 256 threads, 16 rows/block, grid (NN/16, 2)
__global__ void k_mlp2(const float* __restrict__ f1, const float* __restrict__ f2,
                       const float* __restrict__ w1, const float* __restrict__ b1,
                       const float* __restrict__ w2, const float* __restrict__ b2,
                       float* __restrict__ xout)
{
    __shared__ float sf[16 * 512];   // 32KB
    __shared__ float t1[16 * 64];    // 4KB
    int tid = threadIdx.x;
    int v = blockIdx.y;
    const float* feat = v ? f2 : f1;
    int r0 = blockIdx.x * 16;
    const float4* f4 = (const float4*)(feat + (size_t)r0 * 512);
    #pragma unroll
    for (int i = 0; i < 8; i++)
        ((float4*)sf)[tid + i * 256] = f4[tid + i * 256];
    __syncthreads();

    int col = tid & 63, rg = tid >> 6;            // 4 row-groups of 4 rows
    {
        float b = b1[col];
        float a0 = b, a1 = b, a2 = b, a3 = b;
        const float* s0 = sf + (rg * 4 + 0) * 512;
        const float* s1 = sf + (rg * 4 + 1) * 512;
        const float* s2 = sf + (rg * 4 + 2) * 512;
        const float* s3 = sf + (rg * 4 + 3) * 512;
        #pragma unroll 4
        for (int k = 0; k < 512; k++) {
            float wv = w1[k * 64 + col];
            a0 = fmaf(s0[k], wv, a0);
            a1 = fmaf(s1[k], wv, a1);
            a2 = fmaf(s2[k], wv, a2);
            a3 = fmaf(s3[k], wv, a3);
        }
        t1[(rg * 4 + 0) * 64 + col] = fmaxf(a0, 0.f);
        t1[(rg * 4 + 1) * 64 + col] = fmaxf(a1, 0.f);
        t1[(rg * 4 + 2) * 64 + col] = fmaxf(a2, 0.f);
        t1[(rg * 4 + 3) * 64 + col] = fmaxf(a3, 0.f);
    }
    __syncthreads();

    float* xo = xout + (size_t)v * NN * 32;
    #pragma unroll
    for (int o = tid; o < 512; o += 256) {
        int r = o >> 5, c = o & 31;
        float acc = b2[c];
        #pragma unroll
        for (int k = 0; k < 64; k++)
            acc = fmaf(t1[r * 64 + k], w2[k * 32 + c], acc);
        xo[(r0 + r) * 32 + c] = acc;
    }
}

// ---------------- CSR build (both views in each launch) ----------------
__global__ void k_zcnt2(int* __restrict__ cnt)
{
    int i = blockIdx.x * blockDim.x + threadIdx.x;
    if (i < 2 * NN) cnt[i] = 0;
}
__global__ void k_hist2(const int* __restrict__ ei1, const int* __restrict__ ei2,
                        int* __restrict__ cnt, int E)
{
    int e = blockIdx.x * blockDim.x + threadIdx.x;
    int v = blockIdx.y;
    const int* ei = v ? ei2 : ei1;
    if (e < E) atomicAdd(&cnt[v * NN + ei[e]], 1);
}
__global__ void k_scan2(const int* __restrict__ cnt_, int* __restrict__ rowstart_,
                        int* __restrict__ cur_)
{
    __shared__ int ps[1024];
    int b = blockIdx.x;              // view
    const int* cnt = cnt_ + b * NN;
    int* rowstart = rowstart_ + b * (NN + 1);
    int* cur = cur_ + b * NN;
    int t = threadIdx.x;             // 1024 threads
    int loc[8]; int s = 0;
    #pragma unroll
    for (int j = 0; j < 8; j++) { loc[j] = s; s += cnt[t * 8 + j]; }
    ps[t] = s;
    __syncthreads();
    for (int off = 1; off < 1024; off <<= 1) {
        int vv = (t >= off) ? ps[t - off] : 0;
        __syncthreads();
        ps[t] += vv;
        __syncthreads();
    }
    int base = ps[t] - s;            // exclusive base
    #pragma unroll
    for (int j = 0; j < 8; j++) { rowstart[t * 8 + j] = base + loc[j]; cur[t * 8 + j] = base + loc[j]; }
    if (t == 1023) rowstart[NN] = ps[1023];
}
__global__ void k_fill2(const int* __restrict__ ei1, const int* __restrict__ ei2,
                        int* __restrict__ cur, int* __restrict__ eidx, int E)
{
    int e = blockIdx.x * blockDim.x + threadIdx.x;
    int v = blockIdx.y;
    if (e >= E) return;
    const int* ei = v ? ei2 : ei1;
    int p = atomicAdd(&cur[v * NN + ei[e]], 1);
    eidx[v * EMAX + p] = e;
}

// ---------------- 32-dim gather: AX[r][c] = sum_e w_e * X[src_e][c]  (warp per row) ----------------
// Uses A(xW) = (Ax)W: gather in the narrow 32-dim space. 256 thr = 8 warps = 8 rows/block.
__global__ void k_gatherX(const int* __restrict__ rowstart_, const int* __restrict__ eidx_,
                          const int* __restrict__ ei1, const float* __restrict__ ew1,
                          const int* __restrict__ ei2, const float* __restrict__ ew2,
                          const float* __restrict__ X, float* __restrict__ AX, int E)
{
    int v = blockIdx.y;
    const int* ei = v ? ei2 : ei1;
    const float* ew = v ? ew2 : ew1;
    const int* rowstart = rowstart_ + v * (NN + 1);
    const int* eidx = eidx_ + v * EMAX;
    const float* Xv = X + (size_t)v * NN * 32;

    int wid = threadIdx.x >> 5, lane = threadIdx.x & 31;
    int r = blockIdx.x * 8 + wid;
    int s0 = rowstart[r], s1 = rowstart[r + 1];

    float a0 = 0.f, a1 = 0.f, a2 = 0.f, a3 = 0.f;
    for (int base = s0; base < s1; base += 32) {
        int len = min(32, s1 - base);
        int src = 0; float wv = 0.f;
        if (lane < len) {
            int e = eidx[base + lane];
            src = ei[E + e];
            wv = ew[e];
        }
        int j = 0;
        for (; j + 4 <= len; j += 4) {
            int  s0_ = __shfl_sync(0xFFFFFFFF, src, j);
            int  s1_ = __shfl_sync(0xFFFFFFFF, src, j + 1);
            int  s2_ = __shfl_sync(0xFFFFFFFF, src, j + 2);
            int  s3_ = __shfl_sync(0xFFFFFFFF, src, j + 3);
            float w0 = __shfl_sync(0xFFFFFFFF, wv, j);
            float w1_ = __shfl_sync(0xFFFFFFFF, wv, j + 1);
            float w2_ = __shfl_sync(0xFFFFFFFF, wv, j + 2);
            float w3_ = __shfl_sync(0xFFFFFFFF, wv, j + 3);
            a0 = fmaf(w0,  Xv[(size_t)s0_ * 32 + lane], a0);
            a1 = fmaf(w1_, Xv[(size_t)s1_ * 32 + lane], a1);
            a2 = fmaf(w2_, Xv[(size_t)s2_ * 32 + lane], a2);
            a3 = fmaf(w3_, Xv[(size_t)s3_ * 32 + lane], a3);
        }
        for (; j < len; j++) {
            int  sj = __shfl_sync(0xFFFFFFFF, src, j);
            float wj = __shfl_sync(0xFFFFFFFF, wv, j);
            a0 = fmaf(wj, Xv[(size_t)sj * 32 + lane], a0);
        }
    }
    AX[(size_t)v * NN * 32 + (size_t)r * 32 + lane] = (a0 + a1) + (a2 + a3);
}

// ---------------- h1 = relu(AX @ w_g1 + b_g1)  (32->256), 16 rows/block, both views ----------------
__global__ void k_h1_2(const float* __restrict__ ax, const float* __restrict__ w,
                       const float* __restrict__ b, float* __restrict__ R)
{
    __shared__ float sx[16 * 32];    // 2KB
    int tid = threadIdx.x;           // 256
    int v = blockIdx.y;
    int r0 = blockIdx.x * 16;
    const float* xv = ax + (size_t)v * NN * 32 + (size_t)r0 * 32;
    sx[tid] = xv[tid];
    sx[tid + 256] = xv[tid + 256];
    __syncthreads();

    float bb = b[tid];
    float accs[16];
    #pragma unroll
    for (int r = 0; r < 16; r++) accs[r] = bb;
    #pragma unroll 4
    for (int k = 0; k < 32; k++) {
        float wv = w[k * 256 + tid];
        #pragma unroll
        for (int r = 0; r < 16; r++)
            accs[r] = fmaf(sx[r * 32 + k], wv, accs[r]);
    }
    float* rv = R + (size_t)v * NN * CHID;
    #pragma unroll
    for (int r = 0; r < 16; r++)
        rv[(size_t)(r0 + r) * 256 + tid] = fmaxf(accs[r], 0.f);
}

// ---------------- S2 = R @ w_g2 (256->128), 32 rows/block, both views ----------------
__global__ void k_sup2_2(const float* __restrict__ h, const float* __restrict__ w,
                         float* __restrict__ sup)
{
    __shared__ float sh[32 * 256];   // 32KB
    int tid = threadIdx.x;           // 256
    int v = blockIdx.y;
    int r0 = blockIdx.x * 32;
    const float4* h4 = (const float4*)(h + (size_t)v * NN * CHID + (size_t)r0 * 256);
    #pragma unroll
    for (int i = 0; i < 8; i++)
        ((float4*)sh)[tid + i * 256] = h4[tid + i * 256];
    __syncthreads();

    int col = tid & 127, rg = tid >> 7;          // 2 row-groups of 16 rows
    float accs[16];
    #pragma unroll
    for (int r = 0; r < 16; r++) accs[r] = 0.f;
    const float* shb = sh + rg * 16 * 256;
    #pragma unroll 2
    for (int k = 0; k < 256; k++) {
        float wv = w[k * 128 + col];
        #pragma unroll
        for (int r = 0; r < 16; r++)
            accs[r] = fmaf(shb[r * 256 + k], wv, accs[r]);
    }
    float* sv = sup + (size_t)v * NN * CACT;
    #pragma unroll
    for (int r = 0; r < 16; r++)
        sv[(size_t)(r0 + rg * 16 + r) * 128 + col] = accs[r];
}

// ---------------- 128-dim CSR gather: out[r][c] = b[c] + sum_e w_e*sup[src_e][c] ----------------
__global__ void k_gather2(const int* __restrict__ rowstart_, const int* __restrict__ eidx_,
                          const int* __restrict__ ei1, const float* __restrict__ ew1,
                          const int* __restrict__ ei2, const float* __restrict__ ew2,
                          const float* __restrict__ sup, const float* __restrict__ bias,
                          float* __restrict__ out, int E, int C)
{
    __shared__ int ssrc[128];
    __shared__ float swt[128];
    int v = blockIdx.y;
    const int* ei = v ? ei2 : ei1;
    const float* ew = v ? ew2 : ew1;
    const int* rowstart = rowstart_ + v * (NN + 1);
    const int* eidx = eidx_ + v * EMAX;
    const float* supv = sup + (size_t)v * NN * C;
    float* outv = out + (size_t)v * NN * C;

    int r = blockIdx.x, c = threadIdx.x;     // C threads
    int s0 = rowstart[r], s1 = rowstart[r + 1];
    float acc = bias[c];
    for (int base = s0; base < s1; base += 128) {
        int len = min(128, s1 - base);
        __syncthreads();
        if (c < len) {
            int e = eidx[base + c];
            ssrc[c] = ei[E + e];
            swt[c]  = ew[e];
        }
        __syncthreads();
        float a0 = 0.f, a1 = 0.f, a2 = 0.f, a3 = 0.f;
        int i = 0;
        for (; i + 4 <= len; i += 4) {
            a0 = fmaf(swt[i + 0], supv[(size_t)ssrc[i + 0] * C + c], a0);
            a1 = fmaf(swt[i + 1], supv[(size_t)ssrc[i + 1] * C + c], a1);
            a2 = fmaf(swt[i + 2], supv[(size_t)ssrc[i + 2] * C + c], a2);
            a3 = fmaf(swt[i + 3], supv[(size_t)ssrc[i + 3] * C + c], a3);
        }
        for (; i < len; i++)
            a0 = fmaf(swt[i], supv[(size_t)ssrc[i] * C + c], a0);
        acc += (a0 + a1) + (a2 + a3);
    }
    outv[(size_t)r * C + c] = acc;
}

// ---------------- proj + L2 normalize -> bf16, both views, 8 rows/block ----------------
__global__ void k_proj2(const float* __restrict__ h,
                        const float* __restrict__ w1, const float* __restrict__ b1,
                        const float* __restrict__ w2, const float* __restrict__ b2,
                        __nv_bfloat16* __restrict__ zb1, __nv_bfloat16* __restrict__ zb2)
{
    __shared__ float sh[8 * 128];    // 4KB
    __shared__ float tt[8 * 64];     // 2KB
    __shared__ float val[8 * 128];   // 4KB
    __shared__ float sinv[8];
    int tid = threadIdx.x;           // 256
    int v = blockIdx.y;
    int r0 = blockIdx.x * 8;
    const float* hv = h + (size_t)v * NN * CACT + (size_t)r0 * 128;
    #pragma unroll
    for (int i = 0; i < 4; i++)
        sh[tid + i * 256] = hv[tid + i * 256];
    __syncthreads();

    #pragma unroll
    for (int o = tid; o < 512; o += 256) {
        int r = o >> 6, c = o & 63;
        float a = b1[c];
        #pragma unroll 4
        for (int k = 0; k < 128; k++)
            a = fmaf(sh[r * 128 + k], w1[k * 64 + c], a);
        tt[r * 64 + c] = a > 0.f ? a : expm1f(a);
    }
    __syncthreads();

    float av[4];
    #pragma unroll
    for (int j = 0; j < 4; j++) {
        int o = tid + j * 256;
        int r = o >> 7, c = o & 127;
        float a = b2[c];
        #pragma unroll
        for (int k = 0; k < 64; k++)
            a = fmaf(tt[r * 64 + k], w2[k * 128 + c], a);
        av[j] = a;
        val[o] = a * a;
    }
    __syncthreads();

    int wid = tid >> 5, lane = tid & 31;
    float s = val[wid * 128 + lane] + val[wid * 128 + lane + 32]
            + val[wid * 128 + lane + 64] + val[wid * 128 + lane + 96];
    #pragma unroll
    for (int off = 16; off; off >>= 1)
        s += __shfl_xor_sync(0xFFFFFFFF, s, off);
    if (lane == 0) sinv[wid] = 1.f / fmaxf(sqrtf(s), 1e-12f);
    __syncthreads();

    __nv_bfloat16* zb = v ? zb2 : zb1;
    #pragma unroll
    for (int j = 0; j < 4; j++) {
        int o = tid + j * 256;
        int r = o >> 7, c = o & 127;
        zb[(size_t)(r0 + r) * 128 + c] = __float2bfloat16(av[j] * sinv[r]);
    }
}

// ---------------- zero accumulators ----------------
__global__ void k_zero4(float* a, float* b, float* c, float* d)
{
    int i = blockIdx.x * blockDim.x + threadIdx.x;
    if (i < NN) { a[i] = 0.f; b[i] = 0.f; c[i] = 0.f; d[i] = 0.f; }
}

// ---------------- bf16 HMMA pairwise exp row/col-sums (symmetry-reduced) ----------------
#define LDS_PAIR 136
__global__ void __launch_bounds__(256, 2) k_pair_mma(
    const __nv_bfloat16* __restrict__ Zb1, const __nv_bfloat16* __restrict__ Zb2,
    float* __restrict__ rs11, float* __restrict__ d11,
    float* __restrict__ rs22, float* __restrict__ d22,
    float* __restrict__ rs12, float* __restrict__ d12,
    float* __restrict__ cs12)
{
    int job = blockIdx.z, ti = blockIdx.y, tj = blockIdx.x;
    bool sym = (job < 2);
    if (sym && tj < ti) return;

    extern __shared__ __nv_bfloat16 smp[];
    __nv_bfloat16* As = smp;                       // 128 x 136
    __nv_bfloat16* Bs = smp + 128 * LDS_PAIR;      // 128 x 136

    int tid = threadIdx.x, wid = tid >> 5, lane = tid & 31;
    int wm = wid >> 1, wn = wid & 1;               // warp grid 4x2

    const __nv_bfloat16* A = (job == 1) ? Zb2 : Zb1;
    const __nv_bfloat16* B = (job == 0) ? Zb1 : Zb2;
    float* RS = (job == 0) ? rs11 : (job == 1) ? rs22 : rs12;
    float* CS = (job == 0) ? rs11 : (job == 1) ? rs22 : cs12;
    float* DG = (job == 0) ? d11 : (job == 1) ? d22 : d12;
    bool dtile = (ti == tj);
    bool docol = (job == 2) || (tj > ti);

    const __nv_bfloat16* Ap = A + (size_t)ti * 128 * 128;
    const __nv_bfloat16* Bp = B + (size_t)tj * 128 * 128;
    #pragma unroll
    for (int it = 0; it < 8; it++) {
        int idx = it * 256 + tid;
        int row = idx >> 4, col8 = (idx & 15) * 8;
        *(uint4*)(As + row * LDS_PAIR + col8) = *(const uint4*)(Ap + (size_t)row * 128 + col8);
        *(uint4*)(Bs + row * LDS_PAIR + col8) = *(const uint4*)(Bp + (size_t)row * 128 + col8);
    }
    __syncthreads();

    float acc[2][8][4];
    #pragma unroll
    for (int mt = 0; mt < 2; mt++)
        #pragma unroll
        for (int nt = 0; nt < 8; nt++)
            #pragma unroll
            for (int q = 0; q < 4; q++) acc[mt][nt][q] = 0.f;

    uint32_t a_base = smem_u32(As);
    uint32_t b_base = smem_u32(Bs);
    int lrow = lane & 15, lcol = (lane >> 4) * 8;

    #pragma unroll
    for (int ks = 0; ks < 8; ks++) {
        int k0 = ks * 16;
        uint32_t af[2][4];
        #pragma unroll
        for (int mt = 0; mt < 2; mt++) {
            uint32_t addr = a_base + ((wm * 32 + mt * 16 + lrow) * LDS_PAIR + k0 + lcol) * 2;
            ldsm_x4(af[mt][0], af[mt][1], af[mt][2], af[mt][3], addr);
        }
        uint32_t bf[8][2];
        #pragma unroll
        for (int p = 0; p < 4; p++) {
            uint32_t r0, r1, r2, r3;
            uint32_t addr = b_base + ((wn * 64 + p * 16 + lrow) * LDS_PAIR + k0 + lcol) * 2;
            ldsm_x4(r0, r1, r2, r3, addr);
            bf[2 * p][0] = r0; bf[2 * p][1] = r2;
            bf[2 * p + 1][0] = r1; bf[2 * p + 1][1] = r3;
        }
        #pragma unroll
        for (int mt = 0; mt < 2; mt++)
            #pragma unroll
            for (int nt = 0; nt < 8; nt++)
                mma16816(acc[mt][nt], af[mt][0], af[mt][1], af[mt][2], af[mt][3],
                         bf[nt][0], bf[nt][1]);
    }

    int qp = lane & 3, qr = lane >> 2;
    float rsum[2][2] = {{0.f, 0.f}, {0.f, 0.f}};

    #pragma unroll
    for (int nt = 0; nt < 8; nt++) {
        float c0 = 0.f, c1 = 0.f;
        #pragma unroll
        for (int mt = 0; mt < 2; mt++) {
            #pragma unroll
            for (int q = 0; q < 4; q++) {
                float e = __expf(2.0f * acc[mt][nt][q]);   // 1/TEMP = 2
                rsum[mt][q >> 1] += e;
                if (q & 1) c1 += e; else c0 += e;
                if (dtile) {
                    int col = wn * 64 + nt * 8 + qp * 2 + (q & 1);
                    int row = wm * 32 + mt * 16 + qr + (q >> 1) * 8;
                    if (col == row) DG[ti * 128 + row] = e;
                }
            }
        }
        if (docol) {
            #pragma unroll
            for (int sh = 4; sh <= 16; sh <<= 1) {
                c0 += __shfl_xor_sync(0xFFFFFFFF, c0, sh);
                c1 += __shfl_xor_sync(0xFFFFFFFF, c1, sh);
            }
            if (qr == 0) {
                int col = tj * 128 + wn * 64 + nt * 8 + qp * 2;
                atomicAdd(&CS[col], c0);
                atomicAdd(&CS[col + 1], c1);
            }
        }
    }

    #pragma unroll
    for (int mt = 0; mt < 2; mt++)
        #pragma unroll
        for (int h = 0; h < 2; h++) {
            float v = rsum[mt][h];
            v += __shfl_xor_sync(0xFFFFFFFF, v, 1);
            v += __shfl_xor_sync(0xFFFFFFFF, v, 2);
            if (qp == 0) {
                int row = ti * 128 + wm * 32 + mt * 16 + qr + h * 8;
                atomicAdd(&RS[row], v);
            }
        }
}

// ---------------- final loss reduction ----------------
__global__ void k_loss(const float* __restrict__ rs11, const float* __restrict__ d11,
                       const float* __restrict__ rs22, const float* __restrict__ d22,
                       const float* __restrict__ rs12, const float* __restrict__ cs12,
                       const float* __restrict__ d12, float* __restrict__ out)
{
    __shared__ float red[256];
    int tid = threadIdx.x;
    float s = 0.f;
    for (int i = tid; i < NN; i += 256) {
        float ld = logf(d12[i]);
        float l1 = logf(rs11[i] + rs12[i] - d11[i]) - ld;
        float l2 = logf(rs22[i] + cs12[i] - d22[i]) - ld;
        s += 0.5f * (l1 + l2);
    }
    red[tid] = s;
    __syncthreads();
    for (int st = 128; st; st >>= 1) {
        if (tid < st) red[tid] += red[tid + st];
        __syncthreads();
    }
    if (tid == 0) out[0] = red[0] / (float)NN;
}

// ---------------- launch ----------------
extern "C" void kernel_launch(void* const* d_in, const int* in_sizes, int n_in,
                              void* d_out, int out_size)
{
    const float* feat1 = (const float*)d_in[0];
    const float* feat2 = (const float*)d_in[1];
    const int*   ei1   = (const int*)d_in[2];
    const float* ew1   = (const float*)d_in[3];
    const int*   ei2   = (const int*)d_in[4];
    const float* ew2   = (const float*)d_in[5];
    const float* w_l1a = (const float*)d_in[6];
    const float* b_l1a = (const float*)d_in[7];
    const float* w_l1b = (const float*)d_in[8];
    const float* b_l1b = (const float*)d_in[9];
    const float* w_g1  = (const float*)d_in[10];
    const float* b_g1  = (const float*)d_in[11];
    const float* w_g2  = (const float*)d_in[12];
    const float* b_g2  = (const float*)d_in[13];
    const float* w_fc1 = (const float*)d_in[14];
    const float* b_fc1 = (const float*)d_in[15];
    const float* w_fc2 = (const float*)d_in[16];
    const float* b_fc2 = (const float*)d_in[17];
    int E = in_sizes[3];

    float *X, *AX, *R, *S2, *G2;
    __nv_bfloat16 *Zb1, *Zb2;
    float *rs11, *rs22, *rs12, *cs12, *d11, *d22, *d12;
    int *cnt, *cur, *rowstart, *eidx;
    cudaGetSymbolAddress((void**)&X,  g_X);
    cudaGetSymbolAddress((void**)&AX, g_AX);
    cudaGetSymbolAddress((void**)&R,  g_R);
    cudaGetSymbolAddress((void**)&S2, g_S2);
    cudaGetSymbolAddress((void**)&G2, g_G2);
    cudaGetSymbolAddress((void**)&Zb1, g_Zb1);
    cudaGetSymbolAddress((void**)&Zb2, g_Zb2);
    cudaGetSymbolAddress((void**)&rs11, g_rs11);
    cudaGetSymbolAddress((void**)&rs22, g_rs22);
    cudaGetSymbolAddress((void**)&rs12, g_rs12);
    cudaGetSymbolAddress((void**)&cs12, g_cs12);
    cudaGetSymbolAddress((void**)&d11, g_d11);
    cudaGetSymbolAddress((void**)&d22, g_d22);
    cudaGetSymbolAddress((void**)&d12, g_d12);
    cudaGetSymbolAddress((void**)&cnt, g_cnt);
    cudaGetSymbolAddress((void**)&cur, g_cur);
    cudaGetSymbolAddress((void**)&rowstart, g_rowstart);
    cudaGetSymbolAddress((void**)&eidx, g_eidx);

    const int PAIR_SMEM = 2 * 128 * LDS_PAIR * 2;   // 69632
    cudaFuncSetAttribute(k_pair_mma, cudaFuncAttributeMaxDynamicSharedMemorySize, PAIR_SMEM);

    int eg = (E + 255) / 256;

    // CSR build + encoder. k_mlp2 placed 4th so ncu (-s5 -c1, lands on my 4th
    // launch) profiles a representative dense kernel next round.
    k_zcnt2<<<2 * NN / 256, 256>>>(cnt);                                     // 1
    k_hist2<<<dim3(eg, 2), 256>>>(ei1, ei2, cnt, E);                         // 2
    k_scan2<<<2, 1024>>>(cnt, rowstart, cur);                                // 3
    k_mlp2 <<<dim3(NN / 16, 2), 256>>>(feat1, feat2, w_l1a, b_l1a, w_l1b, b_l1b, X); // 4 (profiled)
    k_fill2<<<dim3(eg, 2), 256>>>(ei1, ei2, cur, eidx, E);                   // 5

    // GCN layer 1 via (Ax)W reorder: 32-dim gather then 32->256 GEMM(+bias+relu)
    k_gatherX<<<dim3(NN / 8, 2), 256>>>(rowstart, eidx, ei1, ew1, ei2, ew2, X, AX, E);
    k_h1_2  <<<dim3(NN / 16, 2), 256>>>(AX, w_g1, b_g1, R);
    // GCN layer 2: GEMM then 128-dim gather (narrow side last)
    k_sup2_2<<<dim3(NN / 32, 2), 256>>>(R, w_g2, S2);
    k_gather2<<<dim3(NN, 2), CACT>>>(rowstart, eidx, ei1, ew1, ei2, ew2, S2, b_g2, G2, E, CACT);
    k_proj2 <<<dim3(NN / 8, 2), 256>>>(G2, w_fc1, b_fc1, w_fc2, b_fc2, Zb1, Zb2);

    k_zero4<<<NN / 256, 256>>>(rs11, rs22, rs12, cs12);

    dim3 gp(64, 64, 3);
    k_pair_mma<<<gp, 256, PAIR_SMEM>>>(Zb1, Zb2, rs11, d11, rs22, d22, rs12, d12, cs12);

    k_loss<<<1, 256>>>(rs11, d11, rs22, d22, rs12, cs12, d12, (float*)d_out);
}

// round 17
// speedup vs baseline: 2.2040x; 1.2945x over previous
#include <cuda_runtime.h>
#include <cuda_bf16.h>
#include <math.h>
#include <stdint.h>

#define NN 8192
#define CHID 256
#define CACT 128
#define EMAX 262144
#define LDS_PAIR 136

// ---------------- scratch (no allocations allowed) ----------------
__device__ float g_X [2 * NN * 32];      // MLP output x, both views
__device__ float g_AX[2 * NN * 32];      // A @ x (32-dim gather result)
__device__ float g_R [2 * NN * CHID];    // relu((AX)@Wg1 + b_g1)
__device__ float g_S2[2 * NN * CACT];    // R @ Wg2
__device__ float g_G2[2 * NN * CACT];    // A @ S2 + b_g2
__device__ __align__(16) __nv_bfloat16 g_Zb1[NN * CACT];
__device__ __align__(16) __nv_bfloat16 g_Zb2[NN * CACT];
__device__ float g_rs11[NN], g_rs22[NN], g_rs12[NN], g_cs12[NN];
__device__ float g_d11[NN], g_d22[NN], g_d12[NN];
__device__ int g_cnt[2 * NN];
__device__ int g_cur[2 * NN];
__device__ int g_rowstart[2 * (NN + 1)];
__device__ int g_eidx[2 * EMAX];

// ================= warp-MMA helpers (sm_80+ PTX, safe for compute_103) =================
__device__ __forceinline__ uint32_t smem_u32(const void* p) {
    uint32_t a;
    asm("{ .reg .u64 t; cvta.to.shared.u64 t, %1; cvt.u32.u64 %0, t; }" : "=r"(a) : "l"(p));
    return a;
}
__device__ __forceinline__ void ldsm_x4(uint32_t& r0, uint32_t& r1, uint32_t& r2, uint32_t& r3,
                                        uint32_t saddr) {
    asm volatile("ldmatrix.sync.aligned.m8n8.x4.shared.b16 {%0,%1,%2,%3}, [%4];"
                 : "=r"(r0), "=r"(r1), "=r"(r2), "=r"(r3) : "r"(saddr));
}
__device__ __forceinline__ void mma16816(float* c, uint32_t a0, uint32_t a1, uint32_t a2,
                                         uint32_t a3, uint32_t b0, uint32_t b1) {
    asm volatile(
        "mma.sync.aligned.m16n8k16.row.col.f32.bf16.bf16.f32 "
        "{%0,%1,%2,%3}, {%4,%5,%6,%7}, {%8,%9}, {%0,%1,%2,%3};"
        : "+f"(c[0]), "+f"(c[1]), "+f"(c[2]), "+f"(c[3])
        : "r"(a0), "r"(a1), "r"(a2), "r"(a3), "r"(b0), "r"(b1));
}
__device__ __forceinline__ uint32_t pack_bf16x2(float lo, float hi) {
    uint32_t r;
    asm("cvt.rn.bf16x2.f32 %0, %1, %2;" : "=r"(r) : "f"(hi), "f"(lo));
    return r;
}

// ---------------- MLP via bf16 MMA: x = relu(feat@w1+b1)@w2+b2  (512->64->32) ----------------
// 128 rows/block, 256 thr = 8 warps (4M x 2N), warp tile 32x32, K streamed in 4x128 chunks.
// fp32->bf16 conversion fused into smem tile loads. Layer2 (64->32) scalar fp32.
__global__ void __launch_bounds__(256, 2) k_mlp_mma(
    const float* __restrict__ f1, const float* __restrict__ f2,
    const float* __restrict__ w1, const float* __restrict__ b1,
    const float* __restrict__ w2, const float* __restrict__ b2,
    float* __restrict__ xout)
{
    extern __shared__ char dsm[];
    __nv_bfloat16* As = (__nv_bfloat16*)dsm;                        // 128 x 136
    __nv_bfloat16* Bs = (__nv_bfloat16*)(dsm + 128 * LDS_PAIR * 2); // 64 x 136
    float* t1 = (float*)dsm;                                        // alias: 128 x 65 fp32

    int tid = threadIdx.x, wid = tid >> 5, lane = tid & 31;
    int wm = wid >> 1, wn = wid & 1;
    int v = blockIdx.y;
    const float* feat = v ? f2 : f1;
    int r0 = blockIdx.x * 128;

    float acc[2][4][4];
    #pragma unroll
    for (int mt = 0; mt < 2; mt++)
        #pragma unroll
        for (int nt = 0; nt < 4; nt++)
            #pragma unroll
            for (int q = 0; q < 4; q++) acc[mt][nt][q] = 0.f;

    uint32_t a_base = smem_u32(As), b_base = smem_u32(Bs);
    int lrow = lane & 15, lcol = (lane >> 4) * 8;

    for (int kc = 0; kc < 4; kc++) {
        __syncthreads();
        // A tile: 128 rows x 128 k, fp32 -> bf16
        #pragma unroll
        for (int it = 0; it < 8; it++) {
            int idx = it * 256 + tid;            // 0..2047 groups of 8
            int row = idx >> 4, c8 = (idx & 15) * 8;
            const float4* src = (const float4*)(feat + (size_t)(r0 + row) * 512 + kc * 128 + c8);
            float4 x0 = src[0], x1 = src[1];
            uint4 o;
            o.x = pack_bf16x2(x0.x, x0.y); o.y = pack_bf16x2(x0.z, x0.w);
            o.z = pack_bf16x2(x1.x, x1.y); o.w = pack_bf16x2(x1.z, x1.w);
            *(uint4*)(As + row * LDS_PAIR + c8) = o;
        }
        // W chunk transposed: Bs[n][k] = w1[(kc*128+k)*64 + n]
        #pragma unroll
        for (int it = 0; it < 32; it++) {
            int idx = it * 256 + tid;            // 0..8191
            int k = idx >> 6, n = idx & 63;
            Bs[n * LDS_PAIR + k] = __float2bfloat16(w1[(size_t)(kc * 128 + k) * 64 + n]);
        }
        __syncthreads();
        #pragma unroll
        for (int ks = 0; ks < 8; ks++) {
            int k0 = ks * 16;
            uint32_t af[2][4];
            #pragma unroll
            for (int mt = 0; mt < 2; mt++) {
                uint32_t addr = a_base + ((wm * 32 + mt * 16 + lrow) * LDS_PAIR + k0 + lcol) * 2;
                ldsm_x4(af[mt][0], af[mt][1], af[mt][2], af[mt][3], addr);
            }
            uint32_t bf[4][2];
            #pragma unroll
            for (int p = 0; p < 2; p++) {
                uint32_t q0, q1, q2, q3;
                uint32_t addr = b_base + ((wn * 32 + p * 16 + lrow) * LDS_PAIR + k0 + lcol) * 2;
                ldsm_x4(q0, q1, q2, q3, addr);
                bf[2 * p][0] = q0; bf[2 * p][1] = q2;
                bf[2 * p + 1][0] = q1; bf[2 * p + 1][1] = q3;
            }
            #pragma unroll
            for (int mt = 0; mt < 2; mt++)
                #pragma unroll
                for (int nt = 0; nt < 4; nt++)
                    mma16816(acc[mt][nt], af[mt][0], af[mt][1], af[mt][2], af[mt][3],
                             bf[nt][0], bf[nt][1]);
        }
    }
    __syncthreads();

    // bias + relu -> t1 (fp32, stride 65; aliases As region)
    int qp = lane & 3, qr = lane >> 2;
    #pragma unroll
    for (int mt = 0; mt < 2; mt++)
        #pragma unroll
        for (int nt = 0; nt < 4; nt++)
            #pragma unroll
            for (int q = 0; q < 4; q++) {
                int r = wm * 32 + mt * 16 + qr + (q >> 1) * 8;
                int c = wn * 32 + nt * 8 + qp * 2 + (q & 1);
                t1[r * 65 + c] = fmaxf(acc[mt][nt][q] + b1[c], 0.f);
            }
    __syncthreads();

    // layer2: 64->32, scalar with 16-row ILP per thread
    int c = tid & 31, rb = tid >> 5;
    float a16[16];
    float bb = b2[c];
    #pragma unroll
    for (int j = 0; j < 16; j++) a16[j] = bb;
    #pragma unroll 2
    for (int k = 0; k < 64; k++) {
        float wv = w2[k * 32 + c];
        #pragma unroll
        for (int j = 0; j < 16; j++)
            a16[j] = fmaf(t1[(rb + 8 * j) * 65 + k], wv, a16[j]);
    }
    float* xo = xout + (size_t)v * NN * 32;
    #pragma unroll
    for (int j = 0; j < 16; j++)
        xo[(size_t)(r0 + rb + 8 * j) * 32 + c] = a16[j];
}

// ---------------- CSR build (both views in each launch) ----------------
__global__ void k_zcnt2(int* __restrict__ cnt)
{
    int i = blockIdx.x * blockDim.x + threadIdx.x;
    if (i < 2 * NN) cnt[i] = 0;
}
__global__ void k_hist2(const int* __restrict__ ei1, const int* __restrict__ ei2,
                        int* __restrict__ cnt, int E)
{
    int e = blockIdx.x * blockDim.x + threadIdx.x;
    int v = blockIdx.y;
    const int* ei = v ? ei2 : ei1;
    if (e < E) atomicAdd(&cnt[v * NN + ei[e]], 1);
}
__global__ void k_scan2(const int* __restrict__ cnt_, int* __restrict__ rowstart_,
                        int* __restrict__ cur_)
{
    __shared__ int ps[1024];
    int b = blockIdx.x;              // view
    const int* cnt = cnt_ + b * NN;
    int* rowstart = rowstart_ + b * (NN + 1);
    int* cur = cur_ + b * NN;
    int t = threadIdx.x;             // 1024 threads
    int loc[8]; int s = 0;
    #pragma unroll
    for (int j = 0; j < 8; j++) { loc[j] = s; s += cnt[t * 8 + j]; }
    ps[t] = s;
    __syncthreads();
    for (int off = 1; off < 1024; off <<= 1) {
        int vv = (t >= off) ? ps[t - off] : 0;
        __syncthreads();
        ps[t] += vv;
        __syncthreads();
    }
    int base = ps[t] - s;            // exclusive base
    #pragma unroll
    for (int j = 0; j < 8; j++) { rowstart[t * 8 + j] = base + loc[j]; cur[t * 8 + j] = base + loc[j]; }
    if (t == 1023) rowstart[NN] = ps[1023];
}
__global__ void k_fill2(const int* __restrict__ ei1, const int* __restrict__ ei2,
                        int* __restrict__ cur, int* __restrict__ eidx, int E)
{
    int e = blockIdx.x * blockDim.x + threadIdx.x;
    int v = blockIdx.y;
    if (e >= E) return;
    const int* ei = v ? ei2 : ei1;
    int p = atomicAdd(&cur[v * NN + ei[e]], 1);
    eidx[v * EMAX + p] = e;
}

// ---------------- 32-dim gather: AX[r][c] = sum_e w_e * X[src_e][c]  (warp per row) ----------------
__global__ void k_gatherX(const int* __restrict__ rowstart_, const int* __restrict__ eidx_,
                          const int* __restrict__ ei1, const float* __restrict__ ew1,
                          const int* __restrict__ ei2, const float* __restrict__ ew2,
                          const float* __restrict__ X, float* __restrict__ AX, int E)
{
    int v = blockIdx.y;
    const int* ei = v ? ei2 : ei1;
    const float* ew = v ? ew2 : ew1;
    const int* rowstart = rowstart_ + v * (NN + 1);
    const int* eidx = eidx_ + v * EMAX;
    const float* Xv = X + (size_t)v * NN * 32;

    int wid = threadIdx.x >> 5, lane = threadIdx.x & 31;
    int r = blockIdx.x * 8 + wid;
    int s0 = rowstart[r], s1 = rowstart[r + 1];

    float a0 = 0.f, a1 = 0.f, a2 = 0.f, a3 = 0.f;
    for (int base = s0; base < s1; base += 32) {
        int len = min(32, s1 - base);
        int src = 0; float wv = 0.f;
        if (lane < len) {
            int e = eidx[base + lane];
            src = ei[E + e];
            wv = ew[e];
        }
        int j = 0;
        for (; j + 4 <= len; j += 4) {
            int  s0_ = __shfl_sync(0xFFFFFFFF, src, j);
            int  s1_ = __shfl_sync(0xFFFFFFFF, src, j + 1);
            int  s2_ = __shfl_sync(0xFFFFFFFF, src, j + 2);
            int  s3_ = __shfl_sync(0xFFFFFFFF, src, j + 3);
            float w0 = __shfl_sync(0xFFFFFFFF, wv, j);
            float w1_ = __shfl_sync(0xFFFFFFFF, wv, j + 1);
            float w2_ = __shfl_sync(0xFFFFFFFF, wv, j + 2);
            float w3_ = __shfl_sync(0xFFFFFFFF, wv, j + 3);
            a0 = fmaf(w0,  Xv[(size_t)s0_ * 32 + lane], a0);
            a1 = fmaf(w1_, Xv[(size_t)s1_ * 32 + lane], a1);
            a2 = fmaf(w2_, Xv[(size_t)s2_ * 32 + lane], a2);
            a3 = fmaf(w3_, Xv[(size_t)s3_ * 32 + lane], a3);
        }
        for (; j < len; j++) {
            int  sj = __shfl_sync(0xFFFFFFFF, src, j);
            float wj = __shfl_sync(0xFFFFFFFF, wv, j);
            a0 = fmaf(wj, Xv[(size_t)sj * 32 + lane], a0);
        }
    }
    AX[(size_t)v * NN * 32 + (size_t)r * 32 + lane] = (a0 + a1) + (a2 + a3);
}

// ---------------- h1 = relu(AX @ w_g1 + b_g1)  (32->256), 16 rows/block, both views ----------------
__global__ void k_h1_2(const float* __restrict__ ax, const float* __restrict__ w,
                       const float* __restrict__ b, float* __restrict__ R)
{
    __shared__ float sx[16 * 32];    // 2KB
    int tid = threadIdx.x;           // 256
    int v = blockIdx.y;
    int r0 = blockIdx.x * 16;
    const float* xv = ax + (size_t)v * NN * 32 + (size_t)r0 * 32;
    sx[tid] = xv[tid];
    sx[tid + 256] = xv[tid + 256];
    __syncthreads();

    float bb = b[tid];
    float accs[16];
    #pragma unroll
    for (int r = 0; r < 16; r++) accs[r] = bb;
    #pragma unroll 4
    for (int k = 0; k < 32; k++) {
        float wv = w[k * 256 + tid];
        #pragma unroll
        for (int r = 0; r < 16; r++)
            accs[r] = fmaf(sx[r * 32 + k], wv, accs[r]);
    }
    float* rv = R + (size_t)v * NN * CHID;
    #pragma unroll
    for (int r = 0; r < 16; r++)
        rv[(size_t)(r0 + r) * 256 + tid] = fmaxf(accs[r], 0.f);
}

// ---------------- S2 = R @ w_g2 via bf16 MMA (256->128), 128 rows/block ----------------
// 8 warps (4M x 2N), warp tile 32x64, K streamed in 2x128 chunks.
__global__ void __launch_bounds__(256, 2) k_sup2_mma(
    const float* __restrict__ R, const float* __restrict__ w, float* __restrict__ sup)
{
    extern __shared__ char dsm[];
    __nv_bfloat16* As = (__nv_bfloat16*)dsm;                        // 128 x 136
    __nv_bfloat16* Bs = (__nv_bfloat16*)(dsm + 128 * LDS_PAIR * 2); // 128 x 136
    float* stg = (float*)dsm;                                       // alias: 128 x 132 fp32

    int tid = threadIdx.x, wid = tid >> 5, lane = tid & 31;
    int wm = wid >> 1, wn = wid & 1;
    int v = blockIdx.y;
    int r0 = blockIdx.x * 128;
    const float* Rv = R + (size_t)v * NN * 256;

    float acc[2][8][4];
    #pragma unroll
    for (int mt = 0; mt < 2; mt++)
        #pragma unroll
        for (int nt = 0; nt < 8; nt++)
            #pragma unroll
            for (int q = 0; q < 4; q++) acc[mt][nt][q] = 0.f;

    uint32_t a_base = smem_u32(As), b_base = smem_u32(Bs);
    int lrow = lane & 15, lcol = (lane >> 4) * 8;

    for (int kc = 0; kc < 2; kc++) {
        __syncthreads();
        // A tile: 128 rows x 128 k of R, fp32 -> bf16
        #pragma unroll
        for (int it = 0; it < 8; it++) {
            int idx = it * 256 + tid;
            int row = idx >> 4, c8 = (idx & 15) * 8;
            const float4* src = (const float4*)(Rv + (size_t)(r0 + row) * 256 + kc * 128 + c8);
            float4 x0 = src[0], x1 = src[1];
            uint4 o;
            o.x = pack_bf16x2(x0.x, x0.y); o.y = pack_bf16x2(x0.z, x0.w);
            o.z = pack_bf16x2(x1.x, x1.y); o.w = pack_bf16x2(x1.z, x1.w);
            *(uint4*)(As + row * LDS_PAIR + c8) = o;
        }
        // W chunk transposed: Bs[n][k] = w[(kc*128+k)*128 + n]
        #pragma unroll
        for (int it = 0; it < 64; it++) {
            int idx = it * 256 + tid;            // 0..16383
            int k = idx >> 7, n = idx & 127;
            Bs[n * LDS_PAIR + k] = __float2bfloat16(w[(size_t)(kc * 128 + k) * 128 + n]);
        }
        __syncthreads();
        #pragma unroll
        for (int ks = 0; ks < 8; ks++) {
            int k0 = ks * 16;
            uint32_t af[2][4];
            #pragma unroll
            for (int mt = 0; mt < 2; mt++) {
                uint32_t addr = a_base + ((wm * 32 + mt * 16 + lrow) * LDS_PAIR + k0 + lcol) * 2;
                ldsm_x4(af[mt][0], af[mt][1], af[mt][2], af[mt][3], addr);
            }
            uint32_t bfr[8][2];
            #pragma unroll
            for (int p = 0; p < 4; p++) {
                uint32_t q0, q1, q2, q3;
                uint32_t addr = b_base + ((wn * 64 + p * 16 + lrow) * LDS_PAIR + k0 + lcol) * 2;
                ldsm_x4(q0, q1, q2, q3, addr);
                bfr[2 * p][0] = q0; bfr[2 * p][1] = q2;
                bfr[2 * p + 1][0] = q1; bfr[2 * p + 1][1] = q3;
            }
            #pragma unroll
            for (int mt = 0; mt < 2; mt++)
                #pragma unroll
                for (int nt = 0; nt < 8; nt++)
                    mma16816(acc[mt][nt], af[mt][0], af[mt][1], af[mt][2], af[mt][3],
                             bfr[nt][0], bfr[nt][1]);
        }
    }
    __syncthreads();

    // stage to smem (fp32, stride 132), then coalesced float4 stores
    int qp = lane & 3, qr = lane >> 2;
    #pragma unroll
    for (int mt = 0; mt < 2; mt++)
        #pragma unroll
        for (int nt = 0; nt < 8; nt++)
            #pragma unroll
            for (int q = 0; q < 4; q++) {
                int r = wm * 32 + mt * 16 + qr + (q >> 1) * 8;
                int c = wn * 64 + nt * 8 + qp * 2 + (q & 1);
                stg[r * 132 + c] = acc[mt][nt][q];
            }
    __syncthreads();
    float* sv = sup + (size_t)v * NN * 128;
    #pragma unroll
    for (int it = 0; it < 16; it++) {
        int idx = it * 256 + tid;                // 0..4095 float4 groups
        int row = idx >> 5, c4 = (idx & 31) * 4;
        float4 t;
        t.x = stg[row * 132 + c4 + 0];
        t.y = stg[row * 132 + c4 + 1];
        t.z = stg[row * 132 + c4 + 2];
        t.w = stg[row * 132 + c4 + 3];
        *(float4*)(sv + (size_t)(r0 + row) * 128 + c4) = t;
    }
}

// ---------------- 128-dim CSR gather: out[r][c] = b[c] + sum_e w_e*sup[src_e][c] ----------------
__global__ void k_gather2(const int* __restrict__ rowstart_, const int* __restrict__ eidx_,
                          const int* __restrict__ ei1, const float* __restrict__ ew1,
                          const int* __restrict__ ei2, const float* __restrict__ ew2,
                          const float* __restrict__ sup, const float* __restrict__ bias,
                          float* __restrict__ out, int E, int C)
{
    __shared__ int ssrc[128];
    __shared__ float swt[128];
    int v = blockIdx.y;
    const int* ei = v ? ei2 : ei1;
    const float* ew = v ? ew2 : ew1;
    const int* rowstart = rowstart_ + v * (NN + 1);
    const int* eidx = eidx_ + v * EMAX;
    const float* supv = sup + (size_t)v * NN * C;
    float* outv = out + (size_t)v * NN * C;

    int r = blockIdx.x, c = threadIdx.x;     // C threads
    int s0 = rowstart[r], s1 = rowstart[r + 1];
    float acc = bias[c];
    for (int base = s0; base < s1; base += 128) {
        int len = min(128, s1 - base);
        __syncthreads();
        if (c < len) {
            int e = eidx[base + c];
            ssrc[c] = ei[E + e];
            swt[c]  = ew[e];
        }
        __syncthreads();
        float a0 = 0.f, a1 = 0.f, a2 = 0.f, a3 = 0.f;
        int i = 0;
        for (; i + 4 <= len; i += 4) {
            a0 = fmaf(swt[i + 0], supv[(size_t)ssrc[i + 0] * C + c], a0);
            a1 = fmaf(swt[i + 1], supv[(size_t)ssrc[i + 1] * C + c], a1);
            a2 = fmaf(swt[i + 2], supv[(size_t)ssrc[i + 2] * C + c], a2);
            a3 = fmaf(swt[i + 3], supv[(size_t)ssrc[i + 3] * C + c], a3);
        }
        for (; i < len; i++)
            a0 = fmaf(swt[i], supv[(size_t)ssrc[i] * C + c], a0);
        acc += (a0 + a1) + (a2 + a3);
    }
    outv[(size_t)r * C + c] = acc;
}

// ---------------- proj + L2 normalize -> bf16, both views, 8 rows/block ----------------
__global__ void k_proj2(const float* __restrict__ h,
                        const float* __restrict__ w1, const float* __restrict__ b1,
                        const float* __restrict__ w2, const float* __restrict__ b2,
                        __nv_bfloat16* __restrict__ zb1, __nv_bfloat16* __restrict__ zb2)
{
    __shared__ float sh[8 * 128];    // 4KB
    __shared__ float tt[8 * 64];     // 2KB
    __shared__ float val[8 * 128];   // 4KB
    __shared__ float sinv[8];
    int tid = threadIdx.x;           // 256
    int v = blockIdx.y;
    int r0 = blockIdx.x * 8;
    const float* hv = h + (size_t)v * NN * CACT + (size_t)r0 * 128;
    #pragma unroll
    for (int i = 0; i < 4; i++)
        sh[tid + i * 256] = hv[tid + i * 256];
    __syncthreads();

    #pragma unroll
    for (int o = tid; o < 512; o += 256) {
        int r = o >> 6, c = o & 63;
        float a = b1[c];
        #pragma unroll 4
        for (int k = 0; k < 128; k++)
            a = fmaf(sh[r * 128 + k], w1[k * 64 + c], a);
        tt[r * 64 + c] = a > 0.f ? a : expm1f(a);
    }
    __syncthreads();

    float av[4];
    #pragma unroll
    for (int j = 0; j < 4; j++) {
        int o = tid + j * 256;
        int r = o >> 7, c = o & 127;
        float a = b2[c];
        #pragma unroll
        for (int k = 0; k < 64; k++)
            a = fmaf(tt[r * 64 + k], w2[k * 128 + c], a);
        av[j] = a;
        val[o] = a * a;
    }
    __syncthreads();

    int wid = tid >> 5, lane = tid & 31;
    float s = val[wid * 128 + lane] + val[wid * 128 + lane + 32]
            + val[wid * 128 + lane + 64] + val[wid * 128 + lane + 96];
    #pragma unroll
    for (int off = 16; off; off >>= 1)
        s += __shfl_xor_sync(0xFFFFFFFF, s, off);
    if (lane == 0) sinv[wid] = 1.f / fmaxf(sqrtf(s), 1e-12f);
    __syncthreads();

    __nv_bfloat16* zb = v ? zb2 : zb1;
    #pragma unroll
    for (int j = 0; j < 4; j++) {
        int o = tid + j * 256;
        int r = o >> 7, c = o & 127;
        zb[(size_t)(r0 + r) * 128 + c] = __float2bfloat16(av[j] * sinv[r]);
    }
}

// ---------------- zero accumulators ----------------
__global__ void k_zero4(float* a, float* b, float* c, float* d)
{
    int i = blockIdx.x * blockDim.x + threadIdx.x;
    if (i < NN) { a[i] = 0.f; b[i] = 0.f; c[i] = 0.f; d[i] = 0.f; }
}

// ---------------- bf16 HMMA pairwise exp row/col-sums (symmetry-reduced) ----------------
__global__ void __launch_bounds__(256, 2) k_pair_mma(
    const __nv_bfloat16* __restrict__ Zb1, const __nv_bfloat16* __restrict__ Zb2,
    float* __restrict__ rs11, float* __restrict__ d11,
    float* __restrict__ rs22, float* __restrict__ d22,
    float* __restrict__ rs12, float* __restrict__ d12,
    float* __restrict__ cs12)
{
    int job = blockIdx.z, ti = blockIdx.y, tj = blockIdx.x;
    bool sym = (job < 2);
    if (sym && tj < ti) return;

    extern __shared__ __nv_bfloat16 smp[];
    __nv_bfloat16* As = smp;                       // 128 x 136
    __nv_bfloat16* Bs = smp + 128 * LDS_PAIR;      // 128 x 136

    int tid = threadIdx.x, wid = tid >> 5, lane = tid & 31;
    int wm = wid >> 1, wn = wid & 1;               // warp grid 4x2

    const __nv_bfloat16* A = (job == 1) ? Zb2 : Zb1;
    const __nv_bfloat16* B = (job == 0) ? Zb1 : Zb2;
    float* RS = (job == 0) ? rs11 : (job == 1) ? rs22 : rs12;
    float* CS = (job == 0) ? rs11 : (job == 1) ? rs22 : cs12;
    float* DG = (job == 0) ? d11 : (job == 1) ? d22 : d12;
    bool dtile = (ti == tj);
    bool docol = (job == 2) || (tj > ti);

    const __nv_bfloat16* Ap = A + (size_t)ti * 128 * 128;
    const __nv_bfloat16* Bp = B + (size_t)tj * 128 * 128;
    #pragma unroll
    for (int it = 0; it < 8; it++) {
        int idx = it * 256 + tid;
        int row = idx >> 4, col8 = (idx & 15) * 8;
        *(uint4*)(As + row * LDS_PAIR + col8) = *(const uint4*)(Ap + (size_t)row * 128 + col8);
        *(uint4*)(Bs + row * LDS_PAIR + col8) = *(const uint4*)(Bp + (size_t)row * 128 + col8);
    }
    __syncthreads();

    float acc[2][8][4];
    #pragma unroll
    for (int mt = 0; mt < 2; mt++)
        #pragma unroll
        for (int nt = 0; nt < 8; nt++)
            #pragma unroll
            for (int q = 0; q < 4; q++) acc[mt][nt][q] = 0.f;

    uint32_t a_base = smem_u32(As);
    uint32_t b_base = smem_u32(Bs);
    int lrow = lane & 15, lcol = (lane >> 4) * 8;

    #pragma unroll
    for (int ks = 0; ks < 8; ks++) {
        int k0 = ks * 16;
        uint32_t af[2][4];
        #pragma unroll
        for (int mt = 0; mt < 2; mt++) {
            uint32_t addr = a_base + ((wm * 32 + mt * 16 + lrow) * LDS_PAIR + k0 + lcol) * 2;
            ldsm_x4(af[mt][0], af[mt][1], af[mt][2], af[mt][3], addr);
        }
        uint32_t bfr[8][2];
        #pragma unroll
        for (int p = 0; p < 4; p++) {
            uint32_t q0, q1, q2, q3;
            uint32_t addr = b_base + ((wn * 64 + p * 16 + lrow) * LDS_PAIR + k0 + lcol) * 2;
            ldsm_x4(q0, q1, q2, q3, addr);
            bfr[2 * p][0] = q0; bfr[2 * p][1] = q2;
            bfr[2 * p + 1][0] = q1; bfr[2 * p + 1][1] = q3;
        }
        #pragma unroll
        for (int mt = 0; mt < 2; mt++)
            #pragma unroll
            for (int nt = 0; nt < 8; nt++)
                mma16816(acc[mt][nt], af[mt][0], af[mt][1], af[mt][2], af[mt][3],
                         bfr[nt][0], bfr[nt][1]);
    }

    int qp = lane & 3, qr = lane >> 2;
    float rsum[2][2] = {{0.f, 0.f}, {0.f, 0.f}};

    #pragma unroll
    for (int nt = 0; nt < 8; nt++) {
        float c0 = 0.f, c1 = 0.f;
        #pragma unroll
        for (int mt = 0; mt < 2; mt++) {
            #pragma unroll
            for (int q = 0; q < 4; q++) {
                float e = __expf(2.0f * acc[mt][nt][q]);   // 1/TEMP = 2
                rsum[mt][q >> 1] += e;
                if (q & 1) c1 += e; else c0 += e;
                if (dtile) {
                    int col = wn * 64 + nt * 8 + qp * 2 + (q & 1);
                    int row = wm * 32 + mt * 16 + qr + (q >> 1) * 8;
                    if (col == row) DG[ti * 128 + row] = e;
                }
            }
        }
        if (docol) {
            #pragma unroll
            for (int sh = 4; sh <= 16; sh <<= 1) {
                c0 += __shfl_xor_sync(0xFFFFFFFF, c0, sh);
                c1 += __shfl_xor_sync(0xFFFFFFFF, c1, sh);
            }
            if (qr == 0) {
                int col = tj * 128 + wn * 64 + nt * 8 + qp * 2;
                atomicAdd(&CS[col], c0);
                atomicAdd(&CS[col + 1], c1);
            }
        }
    }

    #pragma unroll
    for (int mt = 0; mt < 2; mt++)
        #pragma unroll
        for (int h = 0; h < 2; h++) {
            float v = rsum[mt][h];
            v += __shfl_xor_sync(0xFFFFFFFF, v, 1);
            v += __shfl_xor_sync(0xFFFFFFFF, v, 2);
            if (qp == 0) {
                int row = ti * 128 + wm * 32 + mt * 16 + qr + h * 8;
                atomicAdd(&RS[row], v);
            }
        }
}

// ---------------- final loss reduction ----------------
__global__ void k_loss(const float* __restrict__ rs11, const float* __restrict__ d11,
                       const float* __restrict__ rs22, const float* __restrict__ d22,
                       const float* __restrict__ rs12, const float* __restrict__ cs12,
                       const float* __restrict__ d12, float* __restrict__ out)
{
    __shared__ float red[256];
    int tid = threadIdx.x;
    float s = 0.f;
    for (int i = tid; i < NN; i += 256) {
        float ld = logf(d12[i]);
        float l1 = logf(rs11[i] + rs12[i] - d11[i]) - ld;
        float l2 = logf(rs22[i] + cs12[i] - d22[i]) - ld;
        s += 0.5f * (l1 + l2);
    }
    red[tid] = s;
    __syncthreads();
    for (int st = 128; st; st >>= 1) {
        if (tid < st) red[tid] += red[tid + st];
        __syncthreads();
    }
    if (tid == 0) out[0] = red[0] / (float)NN;
}

// ---------------- launch ----------------
extern "C" void kernel_launch(void* const* d_in, const int* in_sizes, int n_in,
                              void* d_out, int out_size)
{
    const float* feat1 = (const float*)d_in[0];
    const float* feat2 = (const float*)d_in[1];
    const int*   ei1   = (const int*)d_in[2];
    const float* ew1   = (const float*)d_in[3];
    const int*   ei2   = (const int*)d_in[4];
    const float* ew2   = (const float*)d_in[5];
    const float* w_l1a = (const float*)d_in[6];
    const float* b_l1a = (const float*)d_in[7];
    const float* w_l1b = (const float*)d_in[8];
    const float* b_l1b = (const float*)d_in[9];
    const float* w_g1  = (const float*)d_in[10];
    const float* b_g1  = (const float*)d_in[11];
    const float* w_g2  = (const float*)d_in[12];
    const float* b_g2  = (const float*)d_in[13];
    const float* w_fc1 = (const float*)d_in[14];
    const float* b_fc1 = (const float*)d_in[15];
    const float* w_fc2 = (const float*)d_in[16];
    const float* b_fc2 = (const float*)d_in[17];
    int E = in_sizes[3];

    float *X, *AX, *R, *S2, *G2;
    __nv_bfloat16 *Zb1, *Zb2;
    float *rs11, *rs22, *rs12, *cs12, *d11, *d22, *d12;
    int *cnt, *cur, *rowstart, *eidx;
    cudaGetSymbolAddress((void**)&X,  g_X);
    cudaGetSymbolAddress((void**)&AX, g_AX);
    cudaGetSymbolAddress((void**)&R,  g_R);
    cudaGetSymbolAddress((void**)&S2, g_S2);
    cudaGetSymbolAddress((void**)&G2, g_G2);
    cudaGetSymbolAddress((void**)&Zb1, g_Zb1);
    cudaGetSymbolAddress((void**)&Zb2, g_Zb2);
    cudaGetSymbolAddress((void**)&rs11, g_rs11);
    cudaGetSymbolAddress((void**)&rs22, g_rs22);
    cudaGetSymbolAddress((void**)&rs12, g_rs12);
    cudaGetSymbolAddress((void**)&cs12, g_cs12);
    cudaGetSymbolAddress((void**)&d11, g_d11);
    cudaGetSymbolAddress((void**)&d22, g_d22);
    cudaGetSymbolAddress((void**)&d12, g_d12);
    cudaGetSymbolAddress((void**)&cnt, g_cnt);
    cudaGetSymbolAddress((void**)&cur, g_cur);
    cudaGetSymbolAddress((void**)&rowstart, g_rowstart);
    cudaGetSymbolAddress((void**)&eidx, g_eidx);

    const int PAIR_SMEM = 2 * 128 * LDS_PAIR * 2;                    // 69632
    const int MLP_SMEM  = 128 * LDS_PAIR * 2 + 64 * LDS_PAIR * 2;    // 52224
    const int SUP2_SMEM = 2 * 128 * LDS_PAIR * 2;                    // 69632
    cudaFuncSetAttribute(k_pair_mma, cudaFuncAttributeMaxDynamicSharedMemorySize, PAIR_SMEM);
    cudaFuncSetAttribute(k_mlp_mma,  cudaFuncAttributeMaxDynamicSharedMemorySize, MLP_SMEM);
    cudaFuncSetAttribute(k_sup2_mma, cudaFuncAttributeMaxDynamicSharedMemorySize, SUP2_SMEM);

    int eg = (E + 255) / 256;

    // k_mlp_mma stays 4th so ncu (-s5 -c1) profiles it next round.
    k_zcnt2<<<2 * NN / 256, 256>>>(cnt);                                     // 1
    k_hist2<<<dim3(eg, 2), 256>>>(ei1, ei2, cnt, E);                         // 2
    k_scan2<<<2, 1024>>>(cnt, rowstart, cur);                                // 3
    k_mlp_mma<<<dim3(NN / 128, 2), 256, MLP_SMEM>>>(feat1, feat2, w_l1a, b_l1a,
                                                    w_l1b, b_l1b, X);        // 4 (profiled)
    k_fill2<<<dim3(eg, 2), 256>>>(ei1, ei2, cur, eidx, E);                   // 5

    // GCN layer 1 via (Ax)W: 32-dim gather then 32->256 GEMM(+bias+relu)
    k_gatherX<<<dim3(NN / 8, 2), 256>>>(rowstart, eidx, ei1, ew1, ei2, ew2, X, AX, E);
    k_h1_2  <<<dim3(NN / 16, 2), 256>>>(AX, w_g1, b_g1, R);
    // GCN layer 2: bf16 MMA GEMM then 128-dim gather
    k_sup2_mma<<<dim3(NN / 128, 2), 256, SUP2_SMEM>>>(R, w_g2, S2);
    k_gather2<<<dim3(NN, 2), CACT>>>(rowstart, eidx, ei1, ew1, ei2, ew2, S2, b_g2, G2, E, CACT);
    k_proj2 <<<dim3(NN / 8, 2), 256>>>(G2, w_fc1, b_fc1, w_fc2, b_fc2, Zb1, Zb2);

    k_zero4<<<NN / 256, 256>>>(rs11, rs22, rs12, cs12);

    dim3 gp(64, 64, 3);
    k_pair_mma<<<gp, 256, PAIR_SMEM>>>(Zb1, Zb2, rs11, d11, rs22, d22, rs12, d12, cs12);

    k_loss<<<1, 256>>>(rs11, d11, rs22, d22, rs12, cs12, d12, (float*)d_out);
}